// round 2
// baseline (speedup 1.0000x reference)
#include <cuda_runtime.h>
#include <math.h>

#define BB 8
#define SS 256
#define NNODE 64
#define DD 512
#define VV 32000
#define M2 (BB * SS)   /* 2048 */
#define LN_EPS 1e-5f

// ---------------- scratch (static device globals; no allocation) ----------------
__device__ __align__(16) float g_Xg[M2 * DD];          // 4 MB  x@Wg_top + bg
__device__ __align__(16) float g_Xu[M2 * DD];          // 4 MB  x@Wu_top + bu
__device__ __align__(16) float g_nodes[2][BB * NNODE * DD]; // 2x1 MB ping-pong state
__device__ __align__(16) float g_cons[M2 * DD];        // 4 MB  consensus [B,S,D]
__device__ __align__(16) float g_ln[M2 * DD];          // 4 MB  layernorm(consensus)

// ---------------- init: nodes0[b,n,:] = manifold[n,:] ----------------
__global__ void init_nodes_kernel(const float* __restrict__ mani) {
    int r = blockIdx.x;          // 0..511 = b*64+n
    int n = r & 63;
    const float* src = mani + (size_t)n * DD;
    float* dst = g_nodes[0] + (size_t)r * DD;
    dst[threadIdx.x]       = src[threadIdx.x];
    dst[threadIdx.x + 256] = src[threadIdx.x + 256];
}

// ---------------- precompute: Xg/Xu = emb[idx] @ W_top + bias ----------------
// grid (16 col-tiles of 32, 32 row-tiles of 64), 256 threads
__global__ __launch_bounds__(256) void precompute_kernel(
    const int* __restrict__ idx, const float* __restrict__ emb,
    const float* __restrict__ Wg, const float* __restrict__ bg,
    const float* __restrict__ Wu, const float* __restrict__ bu)
{
    __shared__ float As[16][68];
    __shared__ float Wgs[16][32];
    __shared__ float Wus[16][32];
    __shared__ int   sidx[64];

    int tid = threadIdx.x;
    int m0 = blockIdx.y * 64;
    int n0 = blockIdx.x * 32;
    if (tid < 64) sidx[tid] = idx[m0 + tid];
    __syncthreads();

    int lm = tid >> 2, lkq = tid & 3;     // A loader: row lm, float4 group lkq
    int lwk = tid >> 4, lwn = tid & 15;   // W loader: row lwk, float2 col lwn
    int ty = tid >> 4, tx = tid & 15;     // compute: rows ty*4.., cols tx*2..

    const float* Arow = emb + (size_t)sidx[lm] * DD + lkq * 4;
    const float* Grow = Wg + (size_t)lwk * DD + n0 + lwn * 2;
    const float* Urow = Wu + (size_t)lwk * DD + n0 + lwn * 2;

    float accg[4][2] = {{0.f,0.f},{0.f,0.f},{0.f,0.f},{0.f,0.f}};
    float accu[4][2] = {{0.f,0.f},{0.f,0.f},{0.f,0.f},{0.f,0.f}};

    float4 pa = *(const float4*)Arow;
    float2 pg = *(const float2*)Grow;
    float2 pu = *(const float2*)Urow;

    for (int kt = 0; kt < 32; ++kt) {
        As[lkq*4+0][lm] = pa.x; As[lkq*4+1][lm] = pa.y;
        As[lkq*4+2][lm] = pa.z; As[lkq*4+3][lm] = pa.w;
        *(float2*)&Wgs[lwk][lwn*2] = pg;
        *(float2*)&Wus[lwk][lwn*2] = pu;
        __syncthreads();
        if (kt < 31) {
            int k0 = (kt + 1) * 16;
            pa = *(const float4*)(Arow + k0);
            pg = *(const float2*)(Grow + (size_t)k0 * DD);
            pu = *(const float2*)(Urow + (size_t)k0 * DD);
        }
        #pragma unroll
        for (int kk = 0; kk < 16; ++kk) {
            float4 a = *(const float4*)&As[kk][ty*4];
            float2 wg = *(const float2*)&Wgs[kk][tx*2];
            float2 wu = *(const float2*)&Wus[kk][tx*2];
            float ar[4] = {a.x, a.y, a.z, a.w};
            #pragma unroll
            for (int i = 0; i < 4; ++i) {
                accg[i][0] = fmaf(ar[i], wg.x, accg[i][0]);
                accg[i][1] = fmaf(ar[i], wg.y, accg[i][1]);
                accu[i][0] = fmaf(ar[i], wu.x, accu[i][0]);
                accu[i][1] = fmaf(ar[i], wu.y, accu[i][1]);
            }
        }
        __syncthreads();
    }

    int col = n0 + tx * 2;
    float bg0 = bg[col], bg1 = bg[col + 1];
    float bu0 = bu[col], bu1 = bu[col + 1];
    #pragma unroll
    for (int i = 0; i < 4; ++i) {
        size_t r = (size_t)(m0 + ty * 4 + i) * DD + col;
        g_Xg[r]     = accg[i][0] + bg0;
        g_Xg[r + 1] = accg[i][1] + bg1;
        g_Xu[r]     = accu[i][0] + bu0;
        g_Xu[r + 1] = accu[i][1] + bu1;
    }
}

// ---------------- one recurrence step ----------------
// grid (16 col-tiles of 32, 8 batches), 256 threads. Row tile = the 64 nodes of batch b.
__global__ __launch_bounds__(256) void step_kernel(
    const float* __restrict__ Wg, const float* __restrict__ Wu, int t)
{
    __shared__ float As[16][68];
    __shared__ float Wgs[16][32];
    __shared__ float Wus[16][32];
    __shared__ float part[16][32];

    const float* nin  = g_nodes[t & 1];
    float*       nout = g_nodes[(t + 1) & 1];
    const float* WgB = Wg + (size_t)DD * DD;   // bottom half rows (nodes part)
    const float* WuB = Wu + (size_t)DD * DD;

    int tid = threadIdx.x;
    int b = blockIdx.y;
    int n0 = blockIdx.x * 32;
    int m0 = b * 64;

    int lm = tid >> 2, lkq = tid & 3;
    int lwk = tid >> 4, lwn = tid & 15;
    int ty = tid >> 4, tx = tid & 15;

    const float* Arow = nin + (size_t)(m0 + lm) * DD + lkq * 4;
    const float* Grow = WgB + (size_t)lwk * DD + n0 + lwn * 2;
    const float* Urow = WuB + (size_t)lwk * DD + n0 + lwn * 2;

    float accg[4][2] = {{0.f,0.f},{0.f,0.f},{0.f,0.f},{0.f,0.f}};
    float accu[4][2] = {{0.f,0.f},{0.f,0.f},{0.f,0.f},{0.f,0.f}};

    float4 pa = *(const float4*)Arow;
    float2 pg = *(const float2*)Grow;
    float2 pu = *(const float2*)Urow;

    for (int kt = 0; kt < 32; ++kt) {
        As[lkq*4+0][lm] = pa.x; As[lkq*4+1][lm] = pa.y;
        As[lkq*4+2][lm] = pa.z; As[lkq*4+3][lm] = pa.w;
        *(float2*)&Wgs[lwk][lwn*2] = pg;
        *(float2*)&Wus[lwk][lwn*2] = pu;
        __syncthreads();
        if (kt < 31) {
            int k0 = (kt + 1) * 16;
            pa = *(const float4*)(Arow + k0);
            pg = *(const float2*)(Grow + (size_t)k0 * DD);
            pu = *(const float2*)(Urow + (size_t)k0 * DD);
        }
        #pragma unroll
        for (int kk = 0; kk < 16; ++kk) {
            float4 a = *(const float4*)&As[kk][ty*4];
            float2 wg = *(const float2*)&Wgs[kk][tx*2];
            float2 wu = *(const float2*)&Wus[kk][tx*2];
            float ar[4] = {a.x, a.y, a.z, a.w};
            #pragma unroll
            for (int i = 0; i < 4; ++i) {
                accg[i][0] = fmaf(ar[i], wg.x, accg[i][0]);
                accg[i][1] = fmaf(ar[i], wg.y, accg[i][1]);
                accu[i][0] = fmaf(ar[i], wu.x, accu[i][0]);
                accu[i][1] = fmaf(ar[i], wu.y, accu[i][1]);
            }
        }
        __syncthreads();
    }

    // epilogue: gate/cand nonlinearity, state update, per-batch consensus
    int col = n0 + tx * 2;
    size_t xoff = (size_t)(b * SS + t) * DD + col;
    float xg0 = g_Xg[xoff], xg1 = g_Xg[xoff + 1];
    float xu0 = g_Xu[xoff], xu1 = g_Xu[xoff + 1];
    float cs0 = 0.f, cs1 = 0.f;
    #pragma unroll
    for (int i = 0; i < 4; ++i) {
        size_t rg = (size_t)(m0 + ty * 4 + i) * DD + col;
        float o0 = nin[rg], o1 = nin[rg + 1];
        float g0 = 1.f / (1.f + expf(-(accg[i][0] + xg0)));
        float g1 = 1.f / (1.f + expf(-(accg[i][1] + xg1)));
        float c0 = tanhf(accu[i][0] + xu0);
        float c1 = tanhf(accu[i][1] + xu1);
        float v0 = g0 * c0 + (1.f - g0) * o0;
        float v1 = g1 * c1 + (1.f - g1) * o1;
        nout[rg] = v0; nout[rg + 1] = v1;
        cs0 += v0; cs1 += v1;
    }
    part[ty][tx*2]     = cs0;
    part[ty][tx*2 + 1] = cs1;
    __syncthreads();
    if (tid < 32) {
        float s = 0.f;
        #pragma unroll
        for (int p = 0; p < 16; ++p) s += part[p][tid];
        g_cons[(size_t)(b * SS + t) * DD + n0 + tid] = s * (1.f / 64.f);
    }
}

// ---------------- layernorm over consensus rows ----------------
__device__ __forceinline__ float warp_sum(float v) {
    v += __shfl_xor_sync(0xffffffffu, v, 16);
    v += __shfl_xor_sync(0xffffffffu, v, 8);
    v += __shfl_xor_sync(0xffffffffu, v, 4);
    v += __shfl_xor_sync(0xffffffffu, v, 2);
    v += __shfl_xor_sync(0xffffffffu, v, 1);
    return v;
}

__global__ __launch_bounds__(128) void ln_kernel(
    const float* __restrict__ lw, const float* __restrict__ lb)
{
    int r = blockIdx.x, tid = threadIdx.x;
    const float* x = g_cons + (size_t)r * DD;
    float4 v = *(const float4*)(x + tid * 4);
    __shared__ float red[4];

    float s = v.x + v.y + v.z + v.w;
    s = warp_sum(s);
    if ((tid & 31) == 0) red[tid >> 5] = s;
    __syncthreads();
    float mu = (red[0] + red[1] + red[2] + red[3]) * (1.f / DD);
    __syncthreads();

    float d0 = v.x - mu, d1 = v.y - mu, d2 = v.z - mu, d3 = v.w - mu;
    float ss = d0*d0 + d1*d1 + d2*d2 + d3*d3;
    ss = warp_sum(ss);
    if ((tid & 31) == 0) red[tid >> 5] = ss;
    __syncthreads();
    float var = (red[0] + red[1] + red[2] + red[3]) * (1.f / DD);
    float inv = rsqrtf(var + LN_EPS);

    float4 w = *(const float4*)(lw + tid * 4);
    float4 bb = *(const float4*)(lb + tid * 4);
    float4 o;
    o.x = d0 * inv * w.x + bb.x;
    o.y = d1 * inv * w.y + bb.y;
    o.z = d2 * inv * w.z + bb.z;
    o.w = d3 * inv * w.w + bb.w;
    *(float4*)(g_ln + (size_t)r * DD + tid * 4) = o;
}

// ---------------- output head: logits = ln @ Wh + bh ----------------
// grid (500 col-tiles of 64, 32 row-tiles of 64), 256 threads, 4x4 microtiles
__global__ __launch_bounds__(256) void out_gemm_kernel(
    const float* __restrict__ Wh, const float* __restrict__ bh,
    float* __restrict__ out)
{
    __shared__ float As[16][68];
    __shared__ float Bs[16][64];

    int tid = threadIdx.x;
    int n0 = blockIdx.x * 64;
    int m0 = blockIdx.y * 64;

    int lm = tid >> 2, lkq = tid & 3;
    int lwk = tid >> 4, lwn = tid & 15;
    int ty = tid >> 4, tx = tid & 15;

    const float* Arow = g_ln + (size_t)(m0 + lm) * DD + lkq * 4;
    const float* Brow = Wh + (size_t)lwk * VV + n0 + lwn * 4;

    float acc[4][4];
    #pragma unroll
    for (int i = 0; i < 4; ++i)
        #pragma unroll
        for (int j = 0; j < 4; ++j) acc[i][j] = 0.f;

    float4 pa = *(const float4*)Arow;
    float4 pb = *(const float4*)Brow;

    for (int kt = 0; kt < 32; ++kt) {
        As[lkq*4+0][lm] = pa.x; As[lkq*4+1][lm] = pa.y;
        As[lkq*4+2][lm] = pa.z; As[lkq*4+3][lm] = pa.w;
        *(float4*)&Bs[lwk][lwn*4] = pb;
        __syncthreads();
        if (kt < 31) {
            int k0 = (kt + 1) * 16;
            pa = *(const float4*)(Arow + k0);
            pb = *(const float4*)(Brow + (size_t)k0 * VV);
        }
        #pragma unroll
        for (int kk = 0; kk < 16; ++kk) {
            float4 a = *(const float4*)&As[kk][ty*4];
            float4 b = *(const float4*)&Bs[kk][tx*4];
            float ar[4] = {a.x, a.y, a.z, a.w};
            float br[4] = {b.x, b.y, b.z, b.w};
            #pragma unroll
            for (int i = 0; i < 4; ++i)
                #pragma unroll
                for (int j = 0; j < 4; ++j)
                    acc[i][j] = fmaf(ar[i], br[j], acc[i][j]);
        }
        __syncthreads();
    }

    float4 b4 = *(const float4*)(bh + n0 + tx * 4);
    #pragma unroll
    for (int i = 0; i < 4; ++i) {
        size_t row = (size_t)(m0 + ty * 4 + i);
        float4 o;
        o.x = acc[i][0] + b4.x;
        o.y = acc[i][1] + b4.y;
        o.z = acc[i][2] + b4.z;
        o.w = acc[i][3] + b4.w;
        *(float4*)(out + row * VV + n0 + tx * 4) = o;
    }
}

// ---------------- launch ----------------
extern "C" void kernel_launch(void* const* d_in, const int* in_sizes, int n_in,
                              void* d_out, int out_size)
{
    const int*   idx  = (const int*)  d_in[0];
    const float* emb  = (const float*)d_in[1];
    const float* mani = (const float*)d_in[2];
    const float* Wg   = (const float*)d_in[3];
    const float* bg   = (const float*)d_in[4];
    const float* Wu   = (const float*)d_in[5];
    const float* bu   = (const float*)d_in[6];
    const float* lw   = (const float*)d_in[7];
    const float* lb   = (const float*)d_in[8];
    const float* Wh   = (const float*)d_in[9];
    const float* bh   = (const float*)d_in[10];
    float* out = (float*)d_out;

    init_nodes_kernel<<<512, 256>>>(mani);
    precompute_kernel<<<dim3(16, 32), 256>>>(idx, emb, Wg, bg, Wu, bu);
    for (int t = 0; t < SS; ++t)
        step_kernel<<<dim3(16, 8), 256>>>(Wg, Wu, t);
    ln_kernel<<<M2, 128>>>(lw, lb);
    out_gemm_kernel<<<dim3(500, 32), 256>>>(Wh, bh, out);
}

// round 7
// speedup vs baseline: 1.0962x; 1.0962x over previous
#include <cuda_runtime.h>
#include <cuda_bf16.h>
#include <math.h>
#include <stdint.h>

#define BB 8
#define SS 256
#define DD 512
#define VV 32000
#define M2 (BB * SS)
#define LN_EPS 1e-5f

// ---------------- device-global scratch (referenced ONLY in device code) ----------------
__device__ __align__(16) float g_Xg[M2 * DD];
__device__ __align__(16) float g_Xu[M2 * DD];
__device__ __align__(16) float g_nodes[2][DD * DD];
__device__ __align__(16) float g_cons[M2 * DD];
__device__ __align__(128) __nv_bfloat16 g_Ah[2][DD * DD];
__device__ __align__(128) __nv_bfloat16 g_Al[2][DD * DD];
__device__ __align__(128) __nv_bfloat16 g_Wgh[DD * DD];
__device__ __align__(128) __nv_bfloat16 g_Wgl[DD * DD];
__device__ __align__(128) __nv_bfloat16 g_Wuh[DD * DD];
__device__ __align__(128) __nv_bfloat16 g_Wul[DD * DD];
__device__ __align__(128) __nv_bfloat16 g_Lh[M2 * DD];
__device__ __align__(128) __nv_bfloat16 g_Ll[M2 * DD];
__device__ __align__(128) __nv_bfloat16 g_Whh[(size_t)VV * DD];
__device__ __align__(128) __nv_bfloat16 g_Whl[(size_t)VV * DD];

// ---------------- helpers (baseline ISA: sm_80-class only) ----------------
__device__ __forceinline__ uint32_t smem_u32(const void* p) {
    uint32_t a;
    asm("{ .reg .u64 t; cvta.to.shared.u64 t, %1; cvt.u32.u64 %0, t; }" : "=r"(a) : "l"(p));
    return a;
}
__device__ __forceinline__ void cp16(uint32_t dst, const void* src) {
    asm volatile("cp.async.cg.shared.global [%0], [%1], 16;" :: "r"(dst), "l"(src) : "memory");
}
#define CP_COMMIT() asm volatile("cp.async.commit_group;" ::: "memory")
#define CP_WAIT1() asm volatile("cp.async.wait_group 1;" ::: "memory")
#define CP_WAIT0() asm volatile("cp.async.wait_group 0;" ::: "memory")

__device__ __forceinline__ void mma_bf16(float* d, const uint32_t* a, const uint32_t* b) {
    asm volatile(
        "mma.sync.aligned.m16n8k16.row.col.f32.bf16.bf16.f32 "
        "{%0,%1,%2,%3}, {%4,%5,%6,%7}, {%8,%9}, {%0,%1,%2,%3};"
        : "+f"(d[0]), "+f"(d[1]), "+f"(d[2]), "+f"(d[3])
        : "r"(a[0]), "r"(a[1]), "r"(a[2]), "r"(a[3]), "r"(b[0]), "r"(b[1]));
}
// A m16 x k16 from tile with 48B row stride (16 bf16 data + 16B pad per row)
__device__ __forceinline__ void ldsm48A(uint32_t* r, uint32_t base, int row0) {
    int lane = threadIdx.x & 31;
    uint32_t addr = base + (uint32_t)(row0 + (lane & 15)) * 48u + (uint32_t)((lane >> 4) << 4);
    asm volatile("ldmatrix.sync.aligned.m8n8.x4.shared.b16 {%0,%1,%2,%3}, [%4];"
        : "=r"(r[0]), "=r"(r[1]), "=r"(r[2]), "=r"(r[3]) : "r"(addr));
}
// B: two n8 x k16 tiles; {r0,r1}=n0..7, {r2,r3}=n8..15
__device__ __forceinline__ void ldsm48B(uint32_t* r, uint32_t base, int n0) {
    int lane = threadIdx.x & 31;
    uint32_t addr = base + (uint32_t)(n0 + (lane & 7) + ((lane >> 4) << 3)) * 48u
                  + (uint32_t)(((lane >> 3) & 1) << 4);
    asm volatile("ldmatrix.sync.aligned.m8n8.x4.shared.b16 {%0,%1,%2,%3}, [%4];"
        : "=r"(r[0]), "=r"(r[1]), "=r"(r[2]), "=r"(r[3]) : "r"(addr));
}
__device__ __forceinline__ void bsplit(float v, __nv_bfloat16& h, __nv_bfloat16& l) {
    h = __float2bfloat16(v);
    l = __float2bfloat16(v - __bfloat162float(h));
}

// ---------------- init: nodes0 + bf16 splits ----------------
__global__ void init_nodes_kernel(const float* __restrict__ mani) {
    int r = blockIdx.x;
    int n = r & 63;
    for (int c = threadIdx.x; c < DD; c += 256) {
        float v = mani[(size_t)n * DD + c];
        g_nodes[0][(size_t)r * DD + c] = v;
        __nv_bfloat16 h, l; bsplit(v, h, l);
        g_Ah[0][(size_t)r * DD + c] = h;
        g_Al[0][(size_t)r * DD + c] = l;
    }
}

// ---------------- transpose + bf16-split: W[k][n] -> O[n][k] hi/lo ----------------
// `which` selects the destination INSIDE device code (host must not take
// addresses of __device__ globals): 0 -> Wg bottom, 1 -> Wu bottom, 2 -> Wh.
__global__ __launch_bounds__(256) void wsplit_kernel(
    const float* __restrict__ W, int ncols, int which)
{
    __nv_bfloat16* Oh = (which == 0) ? g_Wgh : (which == 1) ? g_Wuh : g_Whh;
    __nv_bfloat16* Ol = (which == 0) ? g_Wgl : (which == 1) ? g_Wul : g_Whl;
    __shared__ float tile[32][33];
    int n0 = blockIdx.x * 32, k0 = blockIdx.y * 32;
    int tx = threadIdx.x & 31, ty = threadIdx.x >> 5;
    for (int r = ty; r < 32; r += 8)
        tile[r][tx] = W[(size_t)(k0 + r) * ncols + n0 + tx];
    __syncthreads();
    for (int r = ty; r < 32; r += 8) {
        __nv_bfloat16 h, l; bsplit(tile[tx][r], h, l);
        Oh[(size_t)(n0 + r) * DD + k0 + tx] = h;
        Ol[(size_t)(n0 + r) * DD + k0 + tx] = l;
    }
}

// ---------------- precompute: Xg/Xu = emb[idx] @ W_top + bias (fp32 SIMT) ----------------
__global__ __launch_bounds__(256) void precompute_kernel(
    const int* __restrict__ idx, const float* __restrict__ emb,
    const float* __restrict__ Wg, const float* __restrict__ bg,
    const float* __restrict__ Wu, const float* __restrict__ bu)
{
    __shared__ float As[16][68];
    __shared__ float Wgs[16][32];
    __shared__ float Wus[16][32];
    __shared__ int   sidx[64];

    int tid = threadIdx.x;
    int m0 = blockIdx.y * 64;
    int n0 = blockIdx.x * 32;
    if (tid < 64) sidx[tid] = idx[m0 + tid];
    __syncthreads();

    int lm = tid >> 2, lkq = tid & 3;
    int lwk = tid >> 4, lwn = tid & 15;
    int ty = tid >> 4, tx = tid & 15;

    const float* Arow = emb + (size_t)sidx[lm] * DD + lkq * 4;
    const float* Grow = Wg + (size_t)lwk * DD + n0 + lwn * 2;
    const float* Urow = Wu + (size_t)lwk * DD + n0 + lwn * 2;

    float accg[4][2] = {}, accu[4][2] = {};
    float4 pa = *(const float4*)Arow;
    float2 pg = *(const float2*)Grow;
    float2 pu = *(const float2*)Urow;

    for (int kt = 0; kt < 32; ++kt) {
        As[lkq*4+0][lm] = pa.x; As[lkq*4+1][lm] = pa.y;
        As[lkq*4+2][lm] = pa.z; As[lkq*4+3][lm] = pa.w;
        *(float2*)&Wgs[lwk][lwn*2] = pg;
        *(float2*)&Wus[lwk][lwn*2] = pu;
        __syncthreads();
        if (kt < 31) {
            int k0 = (kt + 1) * 16;
            pa = *(const float4*)(Arow + k0);
            pg = *(const float2*)(Grow + (size_t)k0 * DD);
            pu = *(const float2*)(Urow + (size_t)k0 * DD);
        }
        #pragma unroll
        for (int kk = 0; kk < 16; ++kk) {
            float4 a = *(const float4*)&As[kk][ty*4];
            float2 wg = *(const float2*)&Wgs[kk][tx*2];
            float2 wu = *(const float2*)&Wus[kk][tx*2];
            float ar[4] = {a.x, a.y, a.z, a.w};
            #pragma unroll
            for (int i = 0; i < 4; ++i) {
                accg[i][0] = fmaf(ar[i], wg.x, accg[i][0]);
                accg[i][1] = fmaf(ar[i], wg.y, accg[i][1]);
                accu[i][0] = fmaf(ar[i], wu.x, accu[i][0]);
                accu[i][1] = fmaf(ar[i], wu.y, accu[i][1]);
            }
        }
        __syncthreads();
    }
    int col = n0 + tx * 2;
    float bg0 = bg[col], bg1 = bg[col+1], bu0 = bu[col], bu1 = bu[col+1];
    #pragma unroll
    for (int i = 0; i < 4; ++i) {
        size_t r = (size_t)(m0 + ty * 4 + i) * DD + col;
        g_Xg[r] = accg[i][0] + bg0; g_Xg[r+1] = accg[i][1] + bg1;
        g_Xu[r] = accu[i][0] + bu0; g_Xu[r+1] = accu[i][1] + bu1;
    }
}

// ---------------- HMMA recurrence step ----------------
// grid (8 n-tiles of 64, 8 batches), 256 threads (8 warps: wm=wid&3 rows, wn=wid>>2 cols).
// K pipeline: 32 chunks of 16. Tiles: Ah Al Gh Gl Uh Ul, 64 rows x 48B each.
#define ST_TILE  3072
#define ST_STAGE (6 * ST_TILE)
#define ST_SMEM  (2 * ST_STAGE)   /* 36864 < 48K default */

__device__ __forceinline__ void step_load(uint32_t sb, int stage, int kc, int tid,
    const __nv_bfloat16* Ah, const __nv_bfloat16* Al, int m0, int n0)
{
    uint32_t st = sb + stage * ST_STAGE;
    int half = tid >> 7;
    int w = tid & 127;
    int r = w >> 1, c = w & 1;
    uint32_t doff = (uint32_t)r * 48u + (uint32_t)c * 16u;
    int k0 = kc * 16 + c * 8;
    cp16(st + (uint32_t)half * ST_TILE + doff,
         (half ? Al : Ah) + (size_t)(m0 + r) * DD + k0);
    cp16(st + (uint32_t)(2 + half) * ST_TILE + doff,
         (half ? g_Wgl : g_Wgh) + (size_t)(n0 + r) * DD + k0);
    cp16(st + (uint32_t)(4 + half) * ST_TILE + doff,
         (half ? g_Wul : g_Wuh) + (size_t)(n0 + r) * DD + k0);
    CP_COMMIT();
}

__global__ __launch_bounds__(256) void step_kernel(int t) {
    extern __shared__ __align__(16) char smem[];
    uint32_t sb = smem_u32(smem);
    int tid = threadIdx.x, wid = tid >> 5, lane = tid & 31;
    int wm = wid & 3, wn = wid >> 2;
    int b = blockIdx.y;
    int m0 = b * 64, n0 = blockIdx.x * 64;
    int sIn = t & 1, sOut = sIn ^ 1;
    const __nv_bfloat16* Ah = g_Ah[sIn];
    const __nv_bfloat16* Al = g_Al[sIn];

    float accg[4][4] = {}, accu[4][4] = {};

    step_load(sb, 0, 0, tid, Ah, Al, m0, n0);
    for (int c = 0; c < 32; ++c) {
        if (c < 31) { step_load(sb, (c + 1) & 1, c + 1, tid, Ah, Al, m0, n0); CP_WAIT1(); }
        else        { CP_WAIT0(); }
        __syncthreads();
        uint32_t st = sb + (c & 1) * ST_STAGE;
        uint32_t ah[4], al[4], b0[4], b1[4];
        ldsm48A(ah, st,           wm * 16);
        ldsm48A(al, st + ST_TILE, wm * 16);
        // gate: Ah*Gh + Al*Gh
        ldsm48B(b0, st + 2*ST_TILE, wn * 32);
        ldsm48B(b1, st + 2*ST_TILE, wn * 32 + 16);
        #pragma unroll
        for (int nt = 0; nt < 4; ++nt) {
            const uint32_t* bp = (nt < 2) ? &b0[nt * 2] : &b1[(nt & 1) * 2];
            mma_bf16(accg[nt], ah, bp);
            mma_bf16(accg[nt], al, bp);
        }
        // gate: Ah*Gl
        ldsm48B(b0, st + 3*ST_TILE, wn * 32);
        ldsm48B(b1, st + 3*ST_TILE, wn * 32 + 16);
        #pragma unroll
        for (int nt = 0; nt < 4; ++nt)
            mma_bf16(accg[nt], ah, (nt < 2) ? &b0[nt * 2] : &b1[(nt & 1) * 2]);
        // cand: Ah*Uh + Al*Uh
        ldsm48B(b0, st + 4*ST_TILE, wn * 32);
        ldsm48B(b1, st + 4*ST_TILE, wn * 32 + 16);
        #pragma unroll
        for (int nt = 0; nt < 4; ++nt) {
            const uint32_t* bp = (nt < 2) ? &b0[nt * 2] : &b1[(nt & 1) * 2];
            mma_bf16(accu[nt], ah, bp);
            mma_bf16(accu[nt], al, bp);
        }
        // cand: Ah*Ul
        ldsm48B(b0, st + 5*ST_TILE, wn * 32);
        ldsm48B(b1, st + 5*ST_TILE, wn * 32 + 16);
        #pragma unroll
        for (int nt = 0; nt < 4; ++nt)
            mma_bf16(accu[nt], ah, (nt < 2) ? &b0[nt * 2] : &b1[(nt & 1) * 2]);
        __syncthreads();
    }

    // ---- epilogue: nonlinearity, state update, consensus ----
    float* part = (float*)smem;
    int r0 = wm * 16 + (lane >> 2);
    size_t xb = (size_t)(b * SS + t) * DD;
    const float* nodesIn  = g_nodes[sIn];
    float*       nodesOut = g_nodes[sOut];
    __nv_bfloat16* nH = g_Ah[sOut];
    __nv_bfloat16* nL = g_Al[sOut];

    #pragma unroll
    for (int nt = 0; nt < 4; ++nt) {
        int col = n0 + wn * 32 + nt * 8 + (lane & 3) * 2;
        float xg0 = g_Xg[xb + col], xg1 = g_Xg[xb + col + 1];
        float xu0 = g_Xu[xb + col], xu1 = g_Xu[xb + col + 1];
        float cs0 = 0.f, cs1 = 0.f;
        #pragma unroll
        for (int h = 0; h < 2; ++h) {
            int row = m0 + r0 + h * 8;
            size_t off = (size_t)row * DD + col;
            float old0 = nodesIn[off], old1 = nodesIn[off + 1];
            float gv0 = accg[nt][h * 2 + 0] + xg0;
            float gv1 = accg[nt][h * 2 + 1] + xg1;
            float cv0 = accu[nt][h * 2 + 0] + xu0;
            float cv1 = accu[nt][h * 2 + 1] + xu1;
            float g0 = 1.f / (1.f + __expf(-gv0));
            float g1 = 1.f / (1.f + __expf(-gv1));
            float e0 = __expf(2.f * cv0), e1 = __expf(2.f * cv1);
            float th0 = 1.f - 2.f / (e0 + 1.f);
            float th1 = 1.f - 2.f / (e1 + 1.f);
            float v0 = fmaf(g0, th0 - old0, old0);
            float v1 = fmaf(g1, th1 - old1, old1);
            float2 vv; vv.x = v0; vv.y = v1;
            *(float2*)(nodesOut + off) = vv;
            __nv_bfloat16 h0, l0, h1, l1;
            bsplit(v0, h0, l0); bsplit(v1, h1, l1);
            __nv_bfloat162 ph; ph.x = h0; ph.y = h1;
            __nv_bfloat162 pl; pl.x = l0; pl.y = l1;
            *(__nv_bfloat162*)(nH + off) = ph;
            *(__nv_bfloat162*)(nL + off) = pl;
            cs0 += v0; cs1 += v1;
        }
        #pragma unroll
        for (int s = 4; s <= 16; s <<= 1) {
            cs0 += __shfl_xor_sync(0xffffffffu, cs0, s);
            cs1 += __shfl_xor_sync(0xffffffffu, cs1, s);
        }
        if (lane < 4) {
            int cl = wn * 32 + nt * 8 + lane * 2;
            part[wm * 64 + cl]     = cs0;
            part[wm * 64 + cl + 1] = cs1;
        }
    }
    __syncthreads();
    if (tid < 64) {
        float s = part[tid] + part[64 + tid] + part[128 + tid] + part[192 + tid];
        g_cons[xb + n0 + tid] = s * (1.f / 64.f);
    }
}

// ---------------- layernorm -> bf16 hi/lo ----------------
__device__ __forceinline__ float warp_sum(float v) {
    v += __shfl_xor_sync(0xffffffffu, v, 16);
    v += __shfl_xor_sync(0xffffffffu, v, 8);
    v += __shfl_xor_sync(0xffffffffu, v, 4);
    v += __shfl_xor_sync(0xffffffffu, v, 2);
    v += __shfl_xor_sync(0xffffffffu, v, 1);
    return v;
}
__global__ __launch_bounds__(128) void ln_kernel(
    const float* __restrict__ lw, const float* __restrict__ lb)
{
    int r = blockIdx.x, tid = threadIdx.x;
    const float* x = g_cons + (size_t)r * DD;
    float4 v = *(const float4*)(x + tid * 4);
    __shared__ float red[4];
    float s = warp_sum(v.x + v.y + v.z + v.w);
    if ((tid & 31) == 0) red[tid >> 5] = s;
    __syncthreads();
    float mu = (red[0] + red[1] + red[2] + red[3]) * (1.f / DD);
    __syncthreads();
    float d0 = v.x - mu, d1 = v.y - mu, d2 = v.z - mu, d3 = v.w - mu;
    float ss = warp_sum(d0*d0 + d1*d1 + d2*d2 + d3*d3);
    if ((tid & 31) == 0) red[tid >> 5] = ss;
    __syncthreads();
    float inv = rsqrtf((red[0]+red[1]+red[2]+red[3]) * (1.f / DD) + LN_EPS);
    float4 w = *(const float4*)(lw + tid * 4);
    float4 bb = *(const float4*)(lb + tid * 4);
    float o[4] = { d0*inv*w.x + bb.x, d1*inv*w.y + bb.y, d2*inv*w.z + bb.z, d3*inv*w.w + bb.w };
    size_t base = (size_t)r * DD + tid * 4;
    #pragma unroll
    for (int i = 0; i < 4; ++i) {
        __nv_bfloat16 h, l; bsplit(o[i], h, l);
        g_Lh[base + i] = h; g_Ll[base + i] = l;
    }
}

// ---------------- HMMA output head: 128M x 64N tiles ----------------
#define HD_TA 6144                          /* 128 rows x 48B */
#define HD_TB 3072                          /* 64 rows x 48B */
#define HD_STAGE (2 * HD_TA + 2 * HD_TB)    /* 18432 */
#define HD_SMEM  (2 * HD_STAGE)             /* 36864 < 48K */

__device__ __forceinline__ void head_load(uint32_t sb, int stage, int kc, int tid, int m0, int n0) {
    uint32_t st = sb + stage * HD_STAGE;
    {
        int r = tid >> 1, c = tid & 1;
        uint32_t doff = (uint32_t)r * 48u + (uint32_t)c * 16u;
        int k0 = kc * 16 + c * 8;
        cp16(st + doff,         g_Lh + (size_t)(m0 + r) * DD + k0);
        cp16(st + HD_TA + doff, g_Ll + (size_t)(m0 + r) * DD + k0);
    }
    {
        int half = tid >> 7, w = tid & 127;
        int r = w >> 1, c = w & 1;
        uint32_t doff = (uint32_t)r * 48u + (uint32_t)c * 16u;
        int k0 = kc * 16 + c * 8;
        const __nv_bfloat16* src = (half ? g_Whl : g_Whh) + (size_t)(n0 + r) * DD + k0;
        cp16(st + 2 * HD_TA + (uint32_t)half * HD_TB + doff, src);
    }
    CP_COMMIT();
}

__global__ __launch_bounds__(256) void head_kernel(
    const float* __restrict__ bh, float* __restrict__ out)
{
    extern __shared__ __align__(16) char smem[];
    uint32_t sb = smem_u32(smem);
    int tid = threadIdx.x, wid = tid >> 5, lane = tid & 31;
    int wm = wid & 3, wn = wid >> 2;
    int n0 = blockIdx.x * 64, m0 = blockIdx.y * 128;

    float acc[2][4][4];
    #pragma unroll
    for (int i = 0; i < 2; ++i)
        #pragma unroll
        for (int j = 0; j < 4; ++j)
            #pragma unroll
            for (int k = 0; k < 4; ++k) acc[i][j][k] = 0.f;

    head_load(sb, 0, 0, tid, m0, n0);
    for (int c = 0; c < 32; ++c) {
        if (c < 31) { head_load(sb, (c + 1) & 1, c + 1, tid, m0, n0); CP_WAIT1(); }
        else        { CP_WAIT0(); }
        __syncthreads();
        uint32_t st = sb + (c & 1) * HD_STAGE;
        uint32_t ah[2][4], al[2][4], b0[4], b1[4];
        ldsm48A(ah[0], st,         wm * 32);
        ldsm48A(ah[1], st,         wm * 32 + 16);
        ldsm48A(al[0], st + HD_TA, wm * 32);
        ldsm48A(al[1], st + HD_TA, wm * 32 + 16);
        // hi B: Ah*Bh + Al*Bh
        ldsm48B(b0, st + 2*HD_TA,  wn * 32);
        ldsm48B(b1, st + 2*HD_TA,  wn * 32 + 16);
        #pragma unroll
        for (int nt = 0; nt < 4; ++nt) {
            const uint32_t* bp = (nt < 2) ? &b0[nt * 2] : &b1[(nt & 1) * 2];
            #pragma unroll
            for (int mt = 0; mt < 2; ++mt) {
                mma_bf16(acc[mt][nt], ah[mt], bp);
                mma_bf16(acc[mt][nt], al[mt], bp);
            }
        }
        // lo B: Ah*Bl
        ldsm48B(b0, st + 2*HD_TA + HD_TB, wn * 32);
        ldsm48B(b1, st + 2*HD_TA + HD_TB, wn * 32 + 16);
        #pragma unroll
        for (int nt = 0; nt < 4; ++nt) {
            const uint32_t* bp = (nt < 2) ? &b0[nt * 2] : &b1[(nt & 1) * 2];
            #pragma unroll
            for (int mt = 0; mt < 2; ++mt)
                mma_bf16(acc[mt][nt], ah[mt], bp);
        }
        __syncthreads();
    }

    #pragma unroll
    for (int mt = 0; mt < 2; ++mt) {
        #pragma unroll
        for (int nt = 0; nt < 4; ++nt) {
            int col = n0 + wn * 32 + nt * 8 + (lane & 3) * 2;
            float b0v = __ldg(bh + col), b1v = __ldg(bh + col + 1);
            #pragma unroll
            for (int h = 0; h < 2; ++h) {
                int row = m0 + wm * 32 + mt * 16 + (lane >> 2) + h * 8;
                float2 o;
                o.x = acc[mt][nt][h * 2 + 0] + b0v;
                o.y = acc[mt][nt][h * 2 + 1] + b1v;
                *(float2*)(out + (size_t)row * VV + col) = o;
            }
        }
    }
}

// ---------------- launch ----------------
extern "C" void kernel_launch(void* const* d_in, const int* in_sizes, int n_in,
                              void* d_out, int out_size)
{
    const int*   idx  = (const int*)  d_in[0];
    const float* emb  = (const float*)d_in[1];
    const float* mani = (const float*)d_in[2];
    const float* Wg   = (const float*)d_in[3];
    const float* bg   = (const float*)d_in[4];
    const float* Wu   = (const float*)d_in[5];
    const float* bu   = (const float*)d_in[6];
    const float* lw   = (const float*)d_in[7];
    const float* lb   = (const float*)d_in[8];
    const float* Wh   = (const float*)d_in[9];
    const float* bh   = (const float*)d_in[10];
    float* out = (float*)d_out;

    init_nodes_kernel<<<512, 256>>>(mani);
    wsplit_kernel<<<dim3(16, 16), 256>>>(Wg + (size_t)DD * DD, DD, 0);
    wsplit_kernel<<<dim3(16, 16), 256>>>(Wu + (size_t)DD * DD, DD, 1);
    wsplit_kernel<<<dim3(VV / 32, 16), 256>>>(Wh, VV, 2);
    precompute_kernel<<<dim3(16, 32), 256>>>(idx, emb, Wg, bg, Wu, bu);
    for (int t = 0; t < SS; ++t)
        step_kernel<<<dim3(8, 8), 256, ST_SMEM>>>(t);
    ln_kernel<<<M2, 128>>>(lw, lb);
    head_kernel<<<dim3(VV / 64, M2 / 128), 256, HD_SMEM>>>(bh, out);
}

// round 8
// speedup vs baseline: 2.8404x; 2.5912x over previous
#include <cuda_runtime.h>
#include <cuda_bf16.h>
#include <math.h>
#include <stdint.h>

#define BB 8
#define SS 256
#define DD 512
#define VV 32000
#define M2 (BB * SS)
#define LN_EPS 1e-5f

// ---------------- device-global scratch (referenced ONLY in device code) ----------------
__device__ __align__(16) float g_Xg[M2 * DD];
__device__ __align__(16) float g_Xu[M2 * DD];
__device__ __align__(16) float g_nodes[2][DD * DD];
__device__ __align__(16) float g_cons[M2 * DD];
__device__ __align__(128) __nv_bfloat16 g_Ah[2][DD * DD];
__device__ __align__(128) __nv_bfloat16 g_Al[2][DD * DD];
__device__ __align__(128) __nv_bfloat16 g_Wgh[DD * DD];
__device__ __align__(128) __nv_bfloat16 g_Wgl[DD * DD];
__device__ __align__(128) __nv_bfloat16 g_Wuh[DD * DD];
__device__ __align__(128) __nv_bfloat16 g_Wul[DD * DD];
__device__ __align__(128) __nv_bfloat16 g_Lh[M2 * DD];
__device__ __align__(128) __nv_bfloat16 g_Ll[M2 * DD];
__device__ __align__(128) __nv_bfloat16 g_Whh[(size_t)VV * DD];
__device__ __align__(128) __nv_bfloat16 g_Whl[(size_t)VV * DD];

// ---------------- helpers (baseline ISA: sm_80-class only) ----------------
__device__ __forceinline__ uint32_t smem_u32(const void* p) {
    uint32_t a;
    asm("{ .reg .u64 t; cvta.to.shared.u64 t, %1; cvt.u32.u64 %0, t; }" : "=r"(a) : "l"(p));
    return a;
}
__device__ __forceinline__ void cp16(uint32_t dst, const void* src) {
    asm volatile("cp.async.cg.shared.global [%0], [%1], 16;" :: "r"(dst), "l"(src) : "memory");
}
#define CP_COMMIT() asm volatile("cp.async.commit_group;" ::: "memory")
#define CP_WAIT1() asm volatile("cp.async.wait_group 1;" ::: "memory")
#define CP_WAIT0() asm volatile("cp.async.wait_group 0;" ::: "memory")

__device__ __forceinline__ void mma_bf16(float* d, const uint32_t* a, const uint32_t* b) {
    asm volatile(
        "mma.sync.aligned.m16n8k16.row.col.f32.bf16.bf16.f32 "
        "{%0,%1,%2,%3}, {%4,%5,%6,%7}, {%8,%9}, {%0,%1,%2,%3};"
        : "+f"(d[0]), "+f"(d[1]), "+f"(d[2]), "+f"(d[3])
        : "r"(a[0]), "r"(a[1]), "r"(a[2]), "r"(a[3]), "r"(b[0]), "r"(b[1]));
}
// ---- 48B-stride tiles (head kernel; 16 bf16 data + 16B pad per row) ----
__device__ __forceinline__ void ldsm48A(uint32_t* r, uint32_t base, int row0) {
    int lane = threadIdx.x & 31;
    uint32_t addr = base + (uint32_t)(row0 + (lane & 15)) * 48u + (uint32_t)((lane >> 4) << 4);
    asm volatile("ldmatrix.sync.aligned.m8n8.x4.shared.b16 {%0,%1,%2,%3}, [%4];"
        : "=r"(r[0]), "=r"(r[1]), "=r"(r[2]), "=r"(r[3]) : "r"(addr));
}
__device__ __forceinline__ void ldsm48B(uint32_t* r, uint32_t base, int n0) {
    int lane = threadIdx.x & 31;
    uint32_t addr = base + (uint32_t)(n0 + (lane & 7) + ((lane >> 4) << 3)) * 48u
                  + (uint32_t)(((lane >> 3) & 1) << 4);
    asm volatile("ldmatrix.sync.aligned.m8n8.x4.shared.b16 {%0,%1,%2,%3}, [%4];"
        : "=r"(r[0]), "=r"(r[1]), "=r"(r[2]), "=r"(r[3]) : "r"(addr));
}
// ---- 80B-stride tiles (step kernel; 32 bf16 data + 16B pad per row) ----
__device__ __forceinline__ void ldsm80A(uint32_t* r, uint32_t base, int row0, int ks) {
    int lane = threadIdx.x & 31;
    uint32_t addr = base + (uint32_t)(row0 + (lane & 15)) * 80u
                  + (uint32_t)(ks * 32 + ((lane >> 4) << 4));
    asm volatile("ldmatrix.sync.aligned.m8n8.x4.shared.b16 {%0,%1,%2,%3}, [%4];"
        : "=r"(r[0]), "=r"(r[1]), "=r"(r[2]), "=r"(r[3]) : "r"(addr));
}
__device__ __forceinline__ void ldsm80B(uint32_t* r, uint32_t base, int n0, int ks) {
    int lane = threadIdx.x & 31;
    uint32_t addr = base + (uint32_t)(n0 + (lane & 7) + ((lane >> 4) << 3)) * 80u
                  + (uint32_t)(ks * 32 + (((lane >> 3) & 1) << 4));
    asm volatile("ldmatrix.sync.aligned.m8n8.x4.shared.b16 {%0,%1,%2,%3}, [%4];"
        : "=r"(r[0]), "=r"(r[1]), "=r"(r[2]), "=r"(r[3]) : "r"(addr));
}
__device__ __forceinline__ void bsplit(float v, __nv_bfloat16& h, __nv_bfloat16& l) {
    h = __float2bfloat16(v);
    l = __float2bfloat16(v - __bfloat162float(h));
}

// ---------------- init: nodes0 + bf16 splits ----------------
__global__ void init_nodes_kernel(const float* __restrict__ mani) {
    int r = blockIdx.x;
    int n = r & 63;
    for (int c = threadIdx.x; c < DD; c += 256) {
        float v = mani[(size_t)n * DD + c];
        g_nodes[0][(size_t)r * DD + c] = v;
        __nv_bfloat16 h, l; bsplit(v, h, l);
        g_Ah[0][(size_t)r * DD + c] = h;
        g_Al[0][(size_t)r * DD + c] = l;
    }
}

// ---------------- transpose + bf16-split: W[k][n] -> O[n][k] hi/lo ----------------
// `which` selects destination inside device code: 0 -> Wg bottom, 1 -> Wu bottom, 2 -> Wh.
__global__ __launch_bounds__(256) void wsplit_kernel(
    const float* __restrict__ W, int ncols, int which)
{
    __nv_bfloat16* Oh = (which == 0) ? g_Wgh : (which == 1) ? g_Wuh : g_Whh;
    __nv_bfloat16* Ol = (which == 0) ? g_Wgl : (which == 1) ? g_Wul : g_Whl;
    __shared__ float tile[32][33];
    int n0 = blockIdx.x * 32, k0 = blockIdx.y * 32;
    int tx = threadIdx.x & 31, ty = threadIdx.x >> 5;
    for (int r = ty; r < 32; r += 8)
        tile[r][tx] = W[(size_t)(k0 + r) * ncols + n0 + tx];
    __syncthreads();
    for (int r = ty; r < 32; r += 8) {
        __nv_bfloat16 h, l; bsplit(tile[tx][r], h, l);
        Oh[(size_t)(n0 + r) * DD + k0 + tx] = h;
        Ol[(size_t)(n0 + r) * DD + k0 + tx] = l;
    }
}

// ---------------- precompute: Xg/Xu = emb[idx] @ W_top + bias (fp32 SIMT) ----------------
__global__ __launch_bounds__(256) void precompute_kernel(
    const int* __restrict__ idx, const float* __restrict__ emb,
    const float* __restrict__ Wg, const float* __restrict__ bg,
    const float* __restrict__ Wu, const float* __restrict__ bu)
{
    __shared__ float As[16][68];
    __shared__ float Wgs[16][32];
    __shared__ float Wus[16][32];
    __shared__ int   sidx[64];

    int tid = threadIdx.x;
    int m0 = blockIdx.y * 64;
    int n0 = blockIdx.x * 32;
    if (tid < 64) sidx[tid] = idx[m0 + tid];
    __syncthreads();

    int lm = tid >> 2, lkq = tid & 3;
    int lwk = tid >> 4, lwn = tid & 15;
    int ty = tid >> 4, tx = tid & 15;

    const float* Arow = emb + (size_t)sidx[lm] * DD + lkq * 4;
    const float* Grow = Wg + (size_t)lwk * DD + n0 + lwn * 2;
    const float* Urow = Wu + (size_t)lwk * DD + n0 + lwn * 2;

    float accg[4][2] = {}, accu[4][2] = {};
    float4 pa = *(const float4*)Arow;
    float2 pg = *(const float2*)Grow;
    float2 pu = *(const float2*)Urow;

    for (int kt = 0; kt < 32; ++kt) {
        As[lkq*4+0][lm] = pa.x; As[lkq*4+1][lm] = pa.y;
        As[lkq*4+2][lm] = pa.z; As[lkq*4+3][lm] = pa.w;
        *(float2*)&Wgs[lwk][lwn*2] = pg;
        *(float2*)&Wus[lwk][lwn*2] = pu;
        __syncthreads();
        if (kt < 31) {
            int k0 = (kt + 1) * 16;
            pa = *(const float4*)(Arow + k0);
            pg = *(const float2*)(Grow + (size_t)k0 * DD);
            pu = *(const float2*)(Urow + (size_t)k0 * DD);
        }
        #pragma unroll
        for (int kk = 0; kk < 16; ++kk) {
            float4 a = *(const float4*)&As[kk][ty*4];
            float2 wg = *(const float2*)&Wgs[kk][tx*2];
            float2 wu = *(const float2*)&Wus[kk][tx*2];
            float ar[4] = {a.x, a.y, a.z, a.w};
            #pragma unroll
            for (int i = 0; i < 4; ++i) {
                accg[i][0] = fmaf(ar[i], wg.x, accg[i][0]);
                accg[i][1] = fmaf(ar[i], wg.y, accg[i][1]);
                accu[i][0] = fmaf(ar[i], wu.x, accu[i][0]);
                accu[i][1] = fmaf(ar[i], wu.y, accu[i][1]);
            }
        }
        __syncthreads();
    }
    int col = n0 + tx * 2;
    float bg0 = bg[col], bg1 = bg[col+1], bu0 = bu[col], bu1 = bu[col+1];
    #pragma unroll
    for (int i = 0; i < 4; ++i) {
        size_t r = (size_t)(m0 + ty * 4 + i) * DD + col;
        g_Xg[r] = accg[i][0] + bg0; g_Xg[r+1] = accg[i][1] + bg1;
        g_Xu[r] = accu[i][0] + bu0; g_Xu[r+1] = accu[i][1] + bu1;
    }
}

// ---------------- HMMA recurrence step v2 ----------------
// grid (16 n-tiles of 32, 8 batches) = 128 CTAs, 256 threads (8 warps).
// Warp = 16M x 16N (wm = wid&3 row block, wn = wid>>2 col block).
// K pipeline: 16 chunks of 32, 3 stages, prefetch distance 2, 1 sync/chunk.
// Stage: Ah(64x80B) Al | Gh(32x80B) Gl Uh Ul = 20480B. 3 stages + 512B part.
#define ST_STAGE 20480
#define ST_SMEM  (3 * ST_STAGE + 512)

__device__ __forceinline__ void step_load(uint32_t sb, int stage, int kc, int tid,
    const __nv_bfloat16* Ah, const __nv_bfloat16* Al, int m0, int n0)
{
    uint32_t st = sb + (uint32_t)stage * ST_STAGE;
    // A tiles: 2 x 64 rows x 4 16B-words = 512 words
    #pragma unroll
    for (int i = 0; i < 2; ++i) {
        int j = tid + i * 256;
        int tile = j >> 8, w = j & 255, r = w >> 2, c = w & 3;
        cp16(st + (uint32_t)tile * 5120u + (uint32_t)r * 80u + (uint32_t)c * 16u,
             (tile ? Al : Ah) + (size_t)(m0 + r) * DD + kc * 32 + c * 8);
    }
    // W tiles: 4 x 32 rows x 4 words = 512 words
    #pragma unroll
    for (int i = 0; i < 2; ++i) {
        int j = tid + i * 256;
        int u = j >> 7, w = j & 127, r = w >> 2, c = w & 3;
        const __nv_bfloat16* W =
            (u == 0) ? g_Wgh : (u == 1) ? g_Wgl : (u == 2) ? g_Wuh : g_Wul;
        cp16(st + 10240u + (uint32_t)u * 2560u + (uint32_t)r * 80u + (uint32_t)c * 16u,
             W + (size_t)(n0 + r) * DD + kc * 32 + c * 8);
    }
    CP_COMMIT();
}

__global__ __launch_bounds__(256) void step_kernel(int t) {
    extern __shared__ __align__(16) char smem[];
    uint32_t sb = smem_u32(smem);
    int tid = threadIdx.x, wid = tid >> 5, lane = tid & 31;
    int wm = wid & 3, wn = wid >> 2;   // wn in 0..1
    int b = blockIdx.y;
    int m0 = b * 64, n0 = blockIdx.x * 32;
    int sIn = t & 1, sOut = sIn ^ 1;
    const __nv_bfloat16* Ah = g_Ah[sIn];
    const __nv_bfloat16* Al = g_Al[sIn];

    float accg[2][4] = {}, accu[2][4] = {};

    step_load(sb, 0, 0, tid, Ah, Al, m0, n0);
    step_load(sb, 1, 1, tid, Ah, Al, m0, n0);
    for (int c = 0; c < 16; ++c) {
        if (c < 15) CP_WAIT1(); else CP_WAIT0();
        __syncthreads();
        if (c + 2 < 16) step_load(sb, (c + 2) % 3, c + 2, tid, Ah, Al, m0, n0);
        uint32_t st = sb + (uint32_t)(c % 3) * ST_STAGE;
        #pragma unroll
        for (int ks = 0; ks < 2; ++ks) {
            uint32_t ah[4], al[4], bf[4];
            ldsm80A(ah, st,         wm * 16, ks);
            ldsm80A(al, st + 5120,  wm * 16, ks);
            // gate hi: (Ah + Al) * Gh
            ldsm80B(bf, st + 10240, wn * 16, ks);
            #pragma unroll
            for (int nt = 0; nt < 2; ++nt) {
                mma_bf16(accg[nt], ah, &bf[nt * 2]);
                mma_bf16(accg[nt], al, &bf[nt * 2]);
            }
            // gate lo: Ah * Gl
            ldsm80B(bf, st + 12800, wn * 16, ks);
            #pragma unroll
            for (int nt = 0; nt < 2; ++nt)
                mma_bf16(accg[nt], ah, &bf[nt * 2]);
            // cand hi: (Ah + Al) * Uh
            ldsm80B(bf, st + 15360, wn * 16, ks);
            #pragma unroll
            for (int nt = 0; nt < 2; ++nt) {
                mma_bf16(accu[nt], ah, &bf[nt * 2]);
                mma_bf16(accu[nt], al, &bf[nt * 2]);
            }
            // cand lo: Ah * Ul
            ldsm80B(bf, st + 17920, wn * 16, ks);
            #pragma unroll
            for (int nt = 0; nt < 2; ++nt)
                mma_bf16(accu[nt], ah, &bf[nt * 2]);
        }
    }

    // ---- epilogue: nonlinearity, state update, consensus ----
    float* part = (float*)(smem + 3 * ST_STAGE);   // 4x32 floats, dedicated region
    int r0 = wm * 16 + (lane >> 2);
    size_t xb = (size_t)(b * SS + t) * DD;
    const float* nodesIn  = g_nodes[sIn];
    float*       nodesOut = g_nodes[sOut];
    __nv_bfloat16* nH = g_Ah[sOut];
    __nv_bfloat16* nL = g_Al[sOut];

    #pragma unroll
    for (int nt = 0; nt < 2; ++nt) {
        int col = n0 + wn * 16 + nt * 8 + (lane & 3) * 2;
        float xg0 = g_Xg[xb + col], xg1 = g_Xg[xb + col + 1];
        float xu0 = g_Xu[xb + col], xu1 = g_Xu[xb + col + 1];
        float cs0 = 0.f, cs1 = 0.f;
        #pragma unroll
        for (int h = 0; h < 2; ++h) {
            int row = m0 + r0 + h * 8;
            size_t off = (size_t)row * DD + col;
            float old0 = nodesIn[off], old1 = nodesIn[off + 1];
            float gv0 = accg[nt][h * 2 + 0] + xg0;
            float gv1 = accg[nt][h * 2 + 1] + xg1;
            float cv0 = accu[nt][h * 2 + 0] + xu0;
            float cv1 = accu[nt][h * 2 + 1] + xu1;
            float g0 = 1.f / (1.f + __expf(-gv0));
            float g1 = 1.f / (1.f + __expf(-gv1));
            float e0 = __expf(2.f * cv0), e1 = __expf(2.f * cv1);
            float th0 = 1.f - 2.f / (e0 + 1.f);
            float th1 = 1.f - 2.f / (e1 + 1.f);
            float v0 = fmaf(g0, th0 - old0, old0);
            float v1 = fmaf(g1, th1 - old1, old1);
            float2 vv; vv.x = v0; vv.y = v1;
            *(float2*)(nodesOut + off) = vv;
            __nv_bfloat16 h0, l0, h1, l1;
            bsplit(v0, h0, l0); bsplit(v1, h1, l1);
            __nv_bfloat162 ph; ph.x = h0; ph.y = h1;
            __nv_bfloat162 pl; pl.x = l0; pl.y = l1;
            *(__nv_bfloat162*)(nH + off) = ph;
            *(__nv_bfloat162*)(nL + off) = pl;
            cs0 += v0; cs1 += v1;
        }
        #pragma unroll
        for (int s = 4; s <= 16; s <<= 1) {
            cs0 += __shfl_xor_sync(0xffffffffu, cs0, s);
            cs1 += __shfl_xor_sync(0xffffffffu, cs1, s);
        }
        if (lane < 4) {
            int cl = wn * 16 + nt * 8 + lane * 2;
            part[wm * 32 + cl]     = cs0;
            part[wm * 32 + cl + 1] = cs1;
        }
    }
    __syncthreads();
    if (tid < 32) {
        float s = part[tid] + part[32 + tid] + part[64 + tid] + part[96 + tid];
        g_cons[xb + n0 + tid] = s * (1.f / 64.f);
    }
}

// ---------------- layernorm -> bf16 hi/lo ----------------
__device__ __forceinline__ float warp_sum(float v) {
    v += __shfl_xor_sync(0xffffffffu, v, 16);
    v += __shfl_xor_sync(0xffffffffu, v, 8);
    v += __shfl_xor_sync(0xffffffffu, v, 4);
    v += __shfl_xor_sync(0xffffffffu, v, 2);
    v += __shfl_xor_sync(0xffffffffu, v, 1);
    return v;
}
__global__ __launch_bounds__(128) void ln_kernel(
    const float* __restrict__ lw, const float* __restrict__ lb)
{
    int r = blockIdx.x, tid = threadIdx.x;
    const float* x = g_cons + (size_t)r * DD;
    float4 v = *(const float4*)(x + tid * 4);
    __shared__ float red[4];
    float s = warp_sum(v.x + v.y + v.z + v.w);
    if ((tid & 31) == 0) red[tid >> 5] = s;
    __syncthreads();
    float mu = (red[0] + red[1] + red[2] + red[3]) * (1.f / DD);
    __syncthreads();
    float d0 = v.x - mu, d1 = v.y - mu, d2 = v.z - mu, d3 = v.w - mu;
    float ss = warp_sum(d0*d0 + d1*d1 + d2*d2 + d3*d3);
    if ((tid & 31) == 0) red[tid >> 5] = ss;
    __syncthreads();
    float inv = rsqrtf((red[0]+red[1]+red[2]+red[3]) * (1.f / DD) + LN_EPS);
    float4 w = *(const float4*)(lw + tid * 4);
    float4 bb = *(const float4*)(lb + tid * 4);
    float o[4] = { d0*inv*w.x + bb.x, d1*inv*w.y + bb.y, d2*inv*w.z + bb.z, d3*inv*w.w + bb.w };
    size_t base = (size_t)r * DD + tid * 4;
    #pragma unroll
    for (int i = 0; i < 4; ++i) {
        __nv_bfloat16 h, l; bsplit(o[i], h, l);
        g_Lh[base + i] = h; g_Ll[base + i] = l;
    }
}

// ---------------- HMMA output head: 128M x 64N tiles (proven R7) ----------------
#define HD_TA 6144
#define HD_TB 3072
#define HD_STAGE (2 * HD_TA + 2 * HD_TB)
#define HD_SMEM  (2 * HD_STAGE)

__device__ __forceinline__ void head_load(uint32_t sb, int stage, int kc, int tid, int m0, int n0) {
    uint32_t st = sb + stage * HD_STAGE;
    {
        int r = tid >> 1, c = tid & 1;
        uint32_t doff = (uint32_t)r * 48u + (uint32_t)c * 16u;
        int k0 = kc * 16 + c * 8;
        cp16(st + doff,         g_Lh + (size_t)(m0 + r) * DD + k0);
        cp16(st + HD_TA + doff, g_Ll + (size_t)(m0 + r) * DD + k0);
    }
    {
        int half = tid >> 7, w = tid & 127;
        int r = w >> 1, c = w & 1;
        uint32_t doff = (uint32_t)r * 48u + (uint32_t)c * 16u;
        int k0 = kc * 16 + c * 8;
        const __nv_bfloat16* src = (half ? g_Whl : g_Whh) + (size_t)(n0 + r) * DD + k0;
        cp16(st + 2 * HD_TA + (uint32_t)half * HD_TB + doff, src);
    }
    CP_COMMIT();
}

__global__ __launch_bounds__(256) void head_kernel(
    const float* __restrict__ bh, float* __restrict__ out)
{
    extern __shared__ __align__(16) char smem[];
    uint32_t sb = smem_u32(smem);
    int tid = threadIdx.x, wid = tid >> 5, lane = tid & 31;
    int wm = wid & 3, wn = wid >> 2;
    int n0 = blockIdx.x * 64, m0 = blockIdx.y * 128;

    float acc[2][4][4];
    #pragma unroll
    for (int i = 0; i < 2; ++i)
        #pragma unroll
        for (int j = 0; j < 4; ++j)
            #pragma unroll
            for (int k = 0; k < 4; ++k) acc[i][j][k] = 0.f;

    head_load(sb, 0, 0, tid, m0, n0);
    for (int c = 0; c < 32; ++c) {
        if (c < 31) { head_load(sb, (c + 1) & 1, c + 1, tid, m0, n0); CP_WAIT1(); }
        else        { CP_WAIT0(); }
        __syncthreads();
        uint32_t st = sb + (c & 1) * HD_STAGE;
        uint32_t ah[2][4], al[2][4], b0[4], b1[4];
        ldsm48A(ah[0], st,         wm * 32);
        ldsm48A(ah[1], st,         wm * 32 + 16);
        ldsm48A(al[0], st + HD_TA, wm * 32);
        ldsm48A(al[1], st + HD_TA, wm * 32 + 16);
        ldsm48B(b0, st + 2*HD_TA,  wn * 32);
        ldsm48B(b1, st + 2*HD_TA,  wn * 32 + 16);
        #pragma unroll
        for (int nt = 0; nt < 4; ++nt) {
            const uint32_t* bp = (nt < 2) ? &b0[nt * 2] : &b1[(nt & 1) * 2];
            #pragma unroll
            for (int mt = 0; mt < 2; ++mt) {
                mma_bf16(acc[mt][nt], ah[mt], bp);
                mma_bf16(acc[mt][nt], al[mt], bp);
            }
        }
        ldsm48B(b0, st + 2*HD_TA + HD_TB, wn * 32);
        ldsm48B(b1, st + 2*HD_TA + HD_TB, wn * 32 + 16);
        #pragma unroll
        for (int nt = 0; nt < 4; ++nt) {
            const uint32_t* bp = (nt < 2) ? &b0[nt * 2] : &b1[(nt & 1) * 2];
            #pragma unroll
            for (int mt = 0; mt < 2; ++mt)
                mma_bf16(acc[mt][nt], ah[mt], bp);
        }
        __syncthreads();
    }

    #pragma unroll
    for (int mt = 0; mt < 2; ++mt) {
        #pragma unroll
        for (int nt = 0; nt < 4; ++nt) {
            int col = n0 + wn * 32 + nt * 8 + (lane & 3) * 2;
            float b0v = __ldg(bh + col), b1v = __ldg(bh + col + 1);
            #pragma unroll
            for (int h = 0; h < 2; ++h) {
                int row = m0 + wm * 32 + mt * 16 + (lane >> 2) + h * 8;
                float2 o;
                o.x = acc[mt][nt][h * 2 + 0] + b0v;
                o.y = acc[mt][nt][h * 2 + 1] + b1v;
                *(float2*)(out + (size_t)row * VV + col) = o;
            }
        }
    }
}

// ---------------- launch ----------------
extern "C" void kernel_launch(void* const* d_in, const int* in_sizes, int n_in,
                              void* d_out, int out_size)
{
    const int*   idx  = (const int*)  d_in[0];
    const float* emb  = (const float*)d_in[1];
    const float* mani = (const float*)d_in[2];
    const float* Wg   = (const float*)d_in[3];
    const float* bg   = (const float*)d_in[4];
    const float* Wu   = (const float*)d_in[5];
    const float* bu   = (const float*)d_in[6];
    const float* lw   = (const float*)d_in[7];
    const float* lb   = (const float*)d_in[8];
    const float* Wh   = (const float*)d_in[9];
    const float* bh   = (const float*)d_in[10];
    float* out = (float*)d_out;

    // Unconditional (no static guard); idempotent; not an allocation.
    cudaFuncSetAttribute(step_kernel, cudaFuncAttributeMaxDynamicSharedMemorySize, ST_SMEM);

    init_nodes_kernel<<<512, 256>>>(mani);
    wsplit_kernel<<<dim3(16, 16), 256>>>(Wg + (size_t)DD * DD, DD, 0);
    wsplit_kernel<<<dim3(16, 16), 256>>>(Wu + (size_t)DD * DD, DD, 1);
    wsplit_kernel<<<dim3(VV / 32, 16), 256>>>(Wh, VV, 2);
    precompute_kernel<<<dim3(16, 32), 256>>>(idx, emb, Wg, bg, Wu, bu);
    for (int t = 0; t < SS; ++t)
        step_kernel<<<dim3(16, 8), 256, ST_SMEM>>>(t);
    ln_kernel<<<M2, 128>>>(lw, lb);
    head_kernel<<<dim3(VV / 64, M2 / 128), 256, HD_SMEM>>>(bh, out);
}

// round 9
// speedup vs baseline: 3.7271x; 1.3122x over previous
#include <cuda_runtime.h>
#include <cuda_bf16.h>
#include <math.h>
#include <stdint.h>

#define BB 8
#define SS 256
#define DD 512
#define VV 32000
#define M2 (BB * SS)
#define LN_EPS 1e-5f
#define NCTA 128u

// ---------------- device-global scratch (referenced ONLY in device code) ----------------
__device__ __align__(16) float g_Xg[M2 * DD];
__device__ __align__(16) float g_Xu[M2 * DD];
__device__ __align__(16) float g_nodes[2][DD * DD];
__device__ __align__(16) float g_cons[M2 * DD];
__device__ __align__(128) __nv_bfloat16 g_Ah[2][DD * DD];
__device__ __align__(128) __nv_bfloat16 g_Al[2][DD * DD];
__device__ __align__(128) __nv_bfloat16 g_Wgh[DD * DD];
__device__ __align__(128) __nv_bfloat16 g_Wgl[DD * DD];
__device__ __align__(128) __nv_bfloat16 g_Wuh[DD * DD];
__device__ __align__(128) __nv_bfloat16 g_Wul[DD * DD];
__device__ __align__(128) __nv_bfloat16 g_Lh[M2 * DD];
__device__ __align__(128) __nv_bfloat16 g_Ll[M2 * DD];
__device__ __align__(128) __nv_bfloat16 g_Whh[(size_t)VV * DD];
__device__ __align__(128) __nv_bfloat16 g_Whl[(size_t)VV * DD];
__device__ unsigned g_bar;

// ---------------- helpers (baseline ISA: sm_80-class only) ----------------
__device__ __forceinline__ uint32_t smem_u32(const void* p) {
    uint32_t a;
    asm("{ .reg .u64 t; cvta.to.shared.u64 t, %1; cvt.u32.u64 %0, t; }" : "=r"(a) : "l"(p));
    return a;
}
__device__ __forceinline__ void cp16(uint32_t dst, const void* src) {
    asm volatile("cp.async.cg.shared.global [%0], [%1], 16;" :: "r"(dst), "l"(src) : "memory");
}
#define CP_COMMIT() asm volatile("cp.async.commit_group;" ::: "memory")
#define CP_WAIT1() asm volatile("cp.async.wait_group 1;" ::: "memory")
#define CP_WAIT0() asm volatile("cp.async.wait_group 0;" ::: "memory")

__device__ __forceinline__ void mma_bf16(float* d, const uint32_t* a, const uint32_t* b) {
    asm volatile(
        "mma.sync.aligned.m16n8k16.row.col.f32.bf16.bf16.f32 "
        "{%0,%1,%2,%3}, {%4,%5,%6,%7}, {%8,%9}, {%0,%1,%2,%3};"
        : "+f"(d[0]), "+f"(d[1]), "+f"(d[2]), "+f"(d[3])
        : "r"(a[0]), "r"(a[1]), "r"(a[2]), "r"(a[3]), "r"(b[0]), "r"(b[1]));
}
// ---- 48B-stride tiles (head kernel) ----
__device__ __forceinline__ void ldsm48A(uint32_t* r, uint32_t base, int row0) {
    int lane = threadIdx.x & 31;
    uint32_t addr = base + (uint32_t)(row0 + (lane & 15)) * 48u + (uint32_t)((lane >> 4) << 4);
    asm volatile("ldmatrix.sync.aligned.m8n8.x4.shared.b16 {%0,%1,%2,%3}, [%4];"
        : "=r"(r[0]), "=r"(r[1]), "=r"(r[2]), "=r"(r[3]) : "r"(addr));
}
__device__ __forceinline__ void ldsm48B(uint32_t* r, uint32_t base, int n0) {
    int lane = threadIdx.x & 31;
    uint32_t addr = base + (uint32_t)(n0 + (lane & 7) + ((lane >> 4) << 3)) * 48u
                  + (uint32_t)(((lane >> 3) & 1) << 4);
    asm volatile("ldmatrix.sync.aligned.m8n8.x4.shared.b16 {%0,%1,%2,%3}, [%4];"
        : "=r"(r[0]), "=r"(r[1]), "=r"(r[2]), "=r"(r[3]) : "r"(addr));
}
// ---- 80B-stride A tiles (step kernel; 32 bf16 data + 16B pad per row) ----
__device__ __forceinline__ void ldsm80A(uint32_t* r, uint32_t base, int row0, int ks) {
    int lane = threadIdx.x & 31;
    uint32_t addr = base + (uint32_t)(row0 + (lane & 15)) * 80u
                  + (uint32_t)(ks * 32 + ((lane >> 4) << 4));
    asm volatile("ldmatrix.sync.aligned.m8n8.x4.shared.b16 {%0,%1,%2,%3}, [%4];"
        : "=r"(r[0]), "=r"(r[1]), "=r"(r[2]), "=r"(r[3]) : "r"(addr));
}
// ---- 1040B-stride persistent W tiles (full K=512 per row + 16B pad) ----
__device__ __forceinline__ void ldsmW(uint32_t* r, uint32_t base, int n0, int kc, int ks) {
    int lane = threadIdx.x & 31;
    uint32_t addr = base + (uint32_t)(n0 + (lane & 7) + ((lane >> 4) << 3)) * 1040u
                  + (uint32_t)(kc * 64 + ks * 32 + (((lane >> 3) & 1) << 4));
    asm volatile("ldmatrix.sync.aligned.m8n8.x4.shared.b16 {%0,%1,%2,%3}, [%4];"
        : "=r"(r[0]), "=r"(r[1]), "=r"(r[2]), "=r"(r[3]) : "r"(addr));
}
__device__ __forceinline__ void bsplit(float v, __nv_bfloat16& h, __nv_bfloat16& l) {
    h = __float2bfloat16(v);
    l = __float2bfloat16(v - __bfloat162float(h));
}

// ---------------- init: nodes0 + bf16 splits + barrier reset ----------------
__global__ void init_nodes_kernel(const float* __restrict__ mani) {
    if (blockIdx.x == 0 && threadIdx.x == 0) g_bar = 0u;
    int r = blockIdx.x;
    int n = r & 63;
    for (int c = threadIdx.x; c < DD; c += 256) {
        float v = mani[(size_t)n * DD + c];
        g_nodes[0][(size_t)r * DD + c] = v;
        __nv_bfloat16 h, l; bsplit(v, h, l);
        g_Ah[0][(size_t)r * DD + c] = h;
        g_Al[0][(size_t)r * DD + c] = l;
    }
}

// ---------------- transpose + bf16-split: W[k][n] -> O[n][k] hi/lo ----------------
__global__ __launch_bounds__(256) void wsplit_kernel(
    const float* __restrict__ W, int ncols, int which)
{
    __nv_bfloat16* Oh = (which == 0) ? g_Wgh : (which == 1) ? g_Wuh : g_Whh;
    __nv_bfloat16* Ol = (which == 0) ? g_Wgl : (which == 1) ? g_Wul : g_Whl;
    __shared__ float tile[32][33];
    int n0 = blockIdx.x * 32, k0 = blockIdx.y * 32;
    int tx = threadIdx.x & 31, ty = threadIdx.x >> 5;
    for (int r = ty; r < 32; r += 8)
        tile[r][tx] = W[(size_t)(k0 + r) * ncols + n0 + tx];
    __syncthreads();
    for (int r = ty; r < 32; r += 8) {
        __nv_bfloat16 h, l; bsplit(tile[tx][r], h, l);
        Oh[(size_t)(n0 + r) * DD + k0 + tx] = h;
        Ol[(size_t)(n0 + r) * DD + k0 + tx] = l;
    }
}

// ---------------- precompute: Xg/Xu = emb[idx] @ W_top + bias (fp32 SIMT) ----------------
__global__ __launch_bounds__(256) void precompute_kernel(
    const int* __restrict__ idx, const float* __restrict__ emb,
    const float* __restrict__ Wg, const float* __restrict__ bg,
    const float* __restrict__ Wu, const float* __restrict__ bu)
{
    __shared__ float As[16][68];
    __shared__ float Wgs[16][32];
    __shared__ float Wus[16][32];
    __shared__ int   sidx[64];

    int tid = threadIdx.x;
    int m0 = blockIdx.y * 64;
    int n0 = blockIdx.x * 32;
    if (tid < 64) sidx[tid] = idx[m0 + tid];
    __syncthreads();

    int lm = tid >> 2, lkq = tid & 3;
    int lwk = tid >> 4, lwn = tid & 15;
    int ty = tid >> 4, tx = tid & 15;

    const float* Arow = emb + (size_t)sidx[lm] * DD + lkq * 4;
    const float* Grow = Wg + (size_t)lwk * DD + n0 + lwn * 2;
    const float* Urow = Wu + (size_t)lwk * DD + n0 + lwn * 2;

    float accg[4][2] = {}, accu[4][2] = {};
    float4 pa = *(const float4*)Arow;
    float2 pg = *(const float2*)Grow;
    float2 pu = *(const float2*)Urow;

    for (int kt = 0; kt < 32; ++kt) {
        As[lkq*4+0][lm] = pa.x; As[lkq*4+1][lm] = pa.y;
        As[lkq*4+2][lm] = pa.z; As[lkq*4+3][lm] = pa.w;
        *(float2*)&Wgs[lwk][lwn*2] = pg;
        *(float2*)&Wus[lwk][lwn*2] = pu;
        __syncthreads();
        if (kt < 31) {
            int k0 = (kt + 1) * 16;
            pa = *(const float4*)(Arow + k0);
            pg = *(const float2*)(Grow + (size_t)k0 * DD);
            pu = *(const float2*)(Urow + (size_t)k0 * DD);
        }
        #pragma unroll
        for (int kk = 0; kk < 16; ++kk) {
            float4 a = *(const float4*)&As[kk][ty*4];
            float2 wg = *(const float2*)&Wgs[kk][tx*2];
            float2 wu = *(const float2*)&Wus[kk][tx*2];
            float ar[4] = {a.x, a.y, a.z, a.w};
            #pragma unroll
            for (int i = 0; i < 4; ++i) {
                accg[i][0] = fmaf(ar[i], wg.x, accg[i][0]);
                accg[i][1] = fmaf(ar[i], wg.y, accg[i][1]);
                accu[i][0] = fmaf(ar[i], wu.x, accu[i][0]);
                accu[i][1] = fmaf(ar[i], wu.y, accu[i][1]);
            }
        }
        __syncthreads();
    }
    int col = n0 + tx * 2;
    float bg0 = bg[col], bg1 = bg[col+1], bu0 = bu[col], bu1 = bu[col+1];
    #pragma unroll
    for (int i = 0; i < 4; ++i) {
        size_t r = (size_t)(m0 + ty * 4 + i) * DD + col;
        g_Xg[r] = accg[i][0] + bg0; g_Xg[r+1] = accg[i][1] + bg1;
        g_Xu[r] = accu[i][0] + bu0; g_Xu[r+1] = accu[i][1] + bu1;
    }
}

// ---------------- persistent HMMA recurrence (all 256 steps, one launch) ----------------
// 128 CTAs (bx&15 = n-tile of 32, bx>>4 = batch), 256 threads, 1 CTA/SM (co-resident).
// smem: A stages 3 x 10240 | W 4 x 33280 (1040B rows, full K) | part 512
#define PA_STAGE 10240
#define PW_OFF   30720
#define PW_MAT   33280
#define PPART    163840
#define PS_SMEM  164352

__device__ __forceinline__ void pstepA_load(uint32_t sb, int stage, int kc, int tid,
    const __nv_bfloat16* Ah, const __nv_bfloat16* Al, int m0)
{
    uint32_t st = sb + (uint32_t)stage * PA_STAGE;
    #pragma unroll
    for (int i = 0; i < 2; ++i) {
        int j = tid + i * 256;
        int tile = j >> 8, w = j & 255, r = w >> 2, c = w & 3;
        cp16(st + (uint32_t)tile * 5120u + (uint32_t)r * 80u + (uint32_t)c * 16u,
             (tile ? Al : Ah) + (size_t)(m0 + r) * DD + kc * 32 + c * 8);
    }
    CP_COMMIT();
}

__global__ __launch_bounds__(256) void step_persist_kernel() {
    extern __shared__ __align__(16) char smem[];
    uint32_t sb = smem_u32(smem);
    int tid = threadIdx.x, wid = tid >> 5, lane = tid & 31;
    int wm = wid & 3, wn = wid >> 2;   // wn in 0..1
    int b = blockIdx.x >> 4;
    int m0 = b * 64;
    int n0 = (blockIdx.x & 15) * 32;
    float* part = (float*)(smem + PPART);

    // ---- load persistent W tiles: 4 mats x 32 rows x 64 16B-words ----
    for (int j = tid; j < 8192; j += 256) {
        int m = j >> 11, w = j & 2047, r = w >> 6, c = w & 63;
        const __nv_bfloat16* W =
            (m == 0) ? g_Wgh : (m == 1) ? g_Wgl : (m == 2) ? g_Wuh : g_Wul;
        cp16(sb + PW_OFF + (uint32_t)m * PW_MAT + (uint32_t)r * 1040u + (uint32_t)c * 16u,
             W + (size_t)(n0 + r) * DD + c * 8);
    }
    CP_COMMIT();
    CP_WAIT0();
    __syncthreads();

    uint32_t Wb = sb + PW_OFF;

    for (int t = 0; t < SS; ++t) {
        int sIn = t & 1, sOut = sIn ^ 1;
        const __nv_bfloat16* Ah = g_Ah[sIn];
        const __nv_bfloat16* Al = g_Al[sIn];

        float accg[2][4] = {}, accu[2][4] = {};

        pstepA_load(sb, 0, 0, tid, Ah, Al, m0);
        pstepA_load(sb, 1, 1, tid, Ah, Al, m0);
        for (int c = 0; c < 16; ++c) {
            if (c < 15) CP_WAIT1(); else CP_WAIT0();
            __syncthreads();
            if (c + 2 < 16) pstepA_load(sb, (c + 2) % 3, c + 2, tid, Ah, Al, m0);
            uint32_t st = sb + (uint32_t)(c % 3) * PA_STAGE;
            #pragma unroll
            for (int ks = 0; ks < 2; ++ks) {
                uint32_t ah[4], al[4], bf[4];
                ldsm80A(ah, st,        wm * 16, ks);
                ldsm80A(al, st + 5120, wm * 16, ks);
                // gate hi: (Ah + Al) * Gh
                ldsmW(bf, Wb,              wn * 16, c, ks);
                #pragma unroll
                for (int nt = 0; nt < 2; ++nt) {
                    mma_bf16(accg[nt], ah, &bf[nt * 2]);
                    mma_bf16(accg[nt], al, &bf[nt * 2]);
                }
                // gate lo: Ah * Gl
                ldsmW(bf, Wb + PW_MAT,     wn * 16, c, ks);
                #pragma unroll
                for (int nt = 0; nt < 2; ++nt)
                    mma_bf16(accg[nt], ah, &bf[nt * 2]);
                // cand hi: (Ah + Al) * Uh
                ldsmW(bf, Wb + 2 * PW_MAT, wn * 16, c, ks);
                #pragma unroll
                for (int nt = 0; nt < 2; ++nt) {
                    mma_bf16(accu[nt], ah, &bf[nt * 2]);
                    mma_bf16(accu[nt], al, &bf[nt * 2]);
                }
                // cand lo: Ah * Ul
                ldsmW(bf, Wb + 3 * PW_MAT, wn * 16, c, ks);
                #pragma unroll
                for (int nt = 0; nt < 2; ++nt)
                    mma_bf16(accu[nt], ah, &bf[nt * 2]);
            }
        }

        // ---- epilogue ----
        int r0 = wm * 16 + (lane >> 2);
        size_t xb = (size_t)(b * SS + t) * DD;
        const float* nodesIn  = g_nodes[sIn];
        float*       nodesOut = g_nodes[sOut];
        __nv_bfloat16* nH = g_Ah[sOut];
        __nv_bfloat16* nL = g_Al[sOut];

        #pragma unroll
        for (int nt = 0; nt < 2; ++nt) {
            int col = n0 + wn * 16 + nt * 8 + (lane & 3) * 2;
            float xg0 = g_Xg[xb + col], xg1 = g_Xg[xb + col + 1];
            float xu0 = g_Xu[xb + col], xu1 = g_Xu[xb + col + 1];
            float cs0 = 0.f, cs1 = 0.f;
            #pragma unroll
            for (int h = 0; h < 2; ++h) {
                int row = m0 + r0 + h * 8;
                size_t off = (size_t)row * DD + col;
                float2 oldv = __ldcg((const float2*)(nodesIn + off));  // L2-coherent
                float gv0 = accg[nt][h * 2 + 0] + xg0;
                float gv1 = accg[nt][h * 2 + 1] + xg1;
                float cv0 = accu[nt][h * 2 + 0] + xu0;
                float cv1 = accu[nt][h * 2 + 1] + xu1;
                float g0 = 1.f / (1.f + __expf(-gv0));
                float g1 = 1.f / (1.f + __expf(-gv1));
                float e0 = __expf(2.f * cv0), e1 = __expf(2.f * cv1);
                float th0 = 1.f - 2.f / (e0 + 1.f);
                float th1 = 1.f - 2.f / (e1 + 1.f);
                float v0 = fmaf(g0, th0 - oldv.x, oldv.x);
                float v1 = fmaf(g1, th1 - oldv.y, oldv.y);
                float2 vv; vv.x = v0; vv.y = v1;
                *(float2*)(nodesOut + off) = vv;
                __nv_bfloat16 h0, l0, h1, l1;
                bsplit(v0, h0, l0); bsplit(v1, h1, l1);
                __nv_bfloat162 ph; ph.x = h0; ph.y = h1;
                __nv_bfloat162 pl; pl.x = l0; pl.y = l1;
                *(__nv_bfloat162*)(nH + off) = ph;
                *(__nv_bfloat162*)(nL + off) = pl;
                cs0 += v0; cs1 += v1;
            }
            #pragma unroll
            for (int s = 4; s <= 16; s <<= 1) {
                cs0 += __shfl_xor_sync(0xffffffffu, cs0, s);
                cs1 += __shfl_xor_sync(0xffffffffu, cs1, s);
            }
            if (lane < 4) {
                int cl = wn * 16 + nt * 8 + lane * 2;
                part[wm * 32 + cl]     = cs0;
                part[wm * 32 + cl + 1] = cs1;
            }
        }
        __syncthreads();
        if (tid < 32) {
            float s = part[tid] + part[32 + tid] + part[64 + tid] + part[96 + tid];
            g_cons[xb + n0 + tid] = s * (1.f / 64.f);
        }

        // ---- device-wide barrier (monotonic counter; reset by init kernel) ----
        __threadfence();
        __syncthreads();
        if (tid == 0) {
            atomicAdd(&g_bar, 1u);
            unsigned target = NCTA * (unsigned)(t + 1);
            while (*(volatile unsigned*)&g_bar < target) { }
        }
        __syncthreads();
    }
}

// ---------------- layernorm -> bf16 hi/lo ----------------
__device__ __forceinline__ float warp_sum(float v) {
    v += __shfl_xor_sync(0xffffffffu, v, 16);
    v += __shfl_xor_sync(0xffffffffu, v, 8);
    v += __shfl_xor_sync(0xffffffffu, v, 4);
    v += __shfl_xor_sync(0xffffffffu, v, 2);
    v += __shfl_xor_sync(0xffffffffu, v, 1);
    return v;
}
__global__ __launch_bounds__(128) void ln_kernel(
    const float* __restrict__ lw, const float* __restrict__ lb)
{
    int r = blockIdx.x, tid = threadIdx.x;
    const float* x = g_cons + (size_t)r * DD;
    float4 v = *(const float4*)(x + tid * 4);
    __shared__ float red[4];
    float s = warp_sum(v.x + v.y + v.z + v.w);
    if ((tid & 31) == 0) red[tid >> 5] = s;
    __syncthreads();
    float mu = (red[0] + red[1] + red[2] + red[3]) * (1.f / DD);
    __syncthreads();
    float d0 = v.x - mu, d1 = v.y - mu, d2 = v.z - mu, d3 = v.w - mu;
    float ss = warp_sum(d0*d0 + d1*d1 + d2*d2 + d3*d3);
    if ((tid & 31) == 0) red[tid >> 5] = ss;
    __syncthreads();
    float inv = rsqrtf((red[0]+red[1]+red[2]+red[3]) * (1.f / DD) + LN_EPS);
    float4 w = *(const float4*)(lw + tid * 4);
    float4 bb = *(const float4*)(lb + tid * 4);
    float o[4] = { d0*inv*w.x + bb.x, d1*inv*w.y + bb.y, d2*inv*w.z + bb.z, d3*inv*w.w + bb.w };
    size_t base = (size_t)r * DD + tid * 4;
    #pragma unroll
    for (int i = 0; i < 4; ++i) {
        __nv_bfloat16 h, l; bsplit(o[i], h, l);
        g_Lh[base + i] = h; g_Ll[base + i] = l;
    }
}

// ---------------- HMMA output head: 128M x 64N tiles (proven R7/R8) ----------------
#define HD_TA 6144
#define HD_TB 3072
#define HD_STAGE (2 * HD_TA + 2 * HD_TB)
#define HD_SMEM  (2 * HD_STAGE)

__device__ __forceinline__ void head_load(uint32_t sb, int stage, int kc, int tid, int m0, int n0) {
    uint32_t st = sb + stage * HD_STAGE;
    {
        int r = tid >> 1, c = tid & 1;
        uint32_t doff = (uint32_t)r * 48u + (uint32_t)c * 16u;
        int k0 = kc * 16 + c * 8;
        cp16(st + doff,         g_Lh + (size_t)(m0 + r) * DD + k0);
        cp16(st + HD_TA + doff, g_Ll + (size_t)(m0 + r) * DD + k0);
    }
    {
        int half = tid >> 7, w = tid & 127;
        int r = w >> 1, c = w & 1;
        uint32_t doff = (uint32_t)r * 48u + (uint32_t)c * 16u;
        int k0 = kc * 16 + c * 8;
        const __nv_bfloat16* src = (half ? g_Whl : g_Whh) + (size_t)(n0 + r) * DD + k0;
        cp16(st + 2 * HD_TA + (uint32_t)half * HD_TB + doff, src);
    }
    CP_COMMIT();
}

__global__ __launch_bounds__(256) void head_kernel(
    const float* __restrict__ bh, float* __restrict__ out)
{
    extern __shared__ __align__(16) char smem[];
    uint32_t sb = smem_u32(smem);
    int tid = threadIdx.x, wid = tid >> 5, lane = tid & 31;
    int wm = wid & 3, wn = wid >> 2;
    int n0 = blockIdx.x * 64, m0 = blockIdx.y * 128;

    float acc[2][4][4];
    #pragma unroll
    for (int i = 0; i < 2; ++i)
        #pragma unroll
        for (int j = 0; j < 4; ++j)
            #pragma unroll
            for (int k = 0; k < 4; ++k) acc[i][j][k] = 0.f;

    head_load(sb, 0, 0, tid, m0, n0);
    for (int c = 0; c < 32; ++c) {
        if (c < 31) { head_load(sb, (c + 1) & 1, c + 1, tid, m0, n0); CP_WAIT1(); }
        else        { CP_WAIT0(); }
        __syncthreads();
        uint32_t st = sb + (c & 1) * HD_STAGE;
        uint32_t ah[2][4], al[2][4], b0[4], b1[4];
        ldsm48A(ah[0], st,         wm * 32);
        ldsm48A(ah[1], st,         wm * 32 + 16);
        ldsm48A(al[0], st + HD_TA, wm * 32);
        ldsm48A(al[1], st + HD_TA, wm * 32 + 16);
        ldsm48B(b0, st + 2*HD_TA,  wn * 32);
        ldsm48B(b1, st + 2*HD_TA,  wn * 32 + 16);
        #pragma unroll
        for (int nt = 0; nt < 4; ++nt) {
            const uint32_t* bp = (nt < 2) ? &b0[nt * 2] : &b1[(nt & 1) * 2];
            #pragma unroll
            for (int mt = 0; mt < 2; ++mt) {
                mma_bf16(acc[mt][nt], ah[mt], bp);
                mma_bf16(acc[mt][nt], al[mt], bp);
            }
        }
        ldsm48B(b0, st + 2*HD_TA + HD_TB, wn * 32);
        ldsm48B(b1, st + 2*HD_TA + HD_TB, wn * 32 + 16);
        #pragma unroll
        for (int nt = 0; nt < 4; ++nt) {
            const uint32_t* bp = (nt < 2) ? &b0[nt * 2] : &b1[(nt & 1) * 2];
            #pragma unroll
            for (int mt = 0; mt < 2; ++mt)
                mma_bf16(acc[mt][nt], ah[mt], bp);
        }
        __syncthreads();
    }

    #pragma unroll
    for (int mt = 0; mt < 2; ++mt) {
        #pragma unroll
        for (int nt = 0; nt < 4; ++nt) {
            int col = n0 + wn * 32 + nt * 8 + (lane & 3) * 2;
            float b0v = __ldg(bh + col), b1v = __ldg(bh + col + 1);
            #pragma unroll
            for (int h = 0; h < 2; ++h) {
                int row = m0 + wm * 32 + mt * 16 + (lane >> 2) + h * 8;
                float2 o;
                o.x = acc[mt][nt][h * 2 + 0] + b0v;
                o.y = acc[mt][nt][h * 2 + 1] + b1v;
                *(float2*)(out + (size_t)row * VV + col) = o;
            }
        }
    }
}

// ---------------- launch ----------------
extern "C" void kernel_launch(void* const* d_in, const int* in_sizes, int n_in,
                              void* d_out, int out_size)
{
    const int*   idx  = (const int*)  d_in[0];
    const float* emb  = (const float*)d_in[1];
    const float* mani = (const float*)d_in[2];
    const float* Wg   = (const float*)d_in[3];
    const float* bg   = (const float*)d_in[4];
    const float* Wu   = (const float*)d_in[5];
    const float* bu   = (const float*)d_in[6];
    const float* lw   = (const float*)d_in[7];
    const float* lb   = (const float*)d_in[8];
    const float* Wh   = (const float*)d_in[9];
    const float* bh   = (const float*)d_in[10];
    float* out = (float*)d_out;

    // Unconditional, idempotent, not an allocation.
    cudaFuncSetAttribute(step_persist_kernel, cudaFuncAttributeMaxDynamicSharedMemorySize, PS_SMEM);

    init_nodes_kernel<<<512, 256>>>(mani);
    wsplit_kernel<<<dim3(16, 16), 256>>>(Wg + (size_t)DD * DD, DD, 0);
    wsplit_kernel<<<dim3(16, 16), 256>>>(Wu + (size_t)DD * DD, DD, 1);
    wsplit_kernel<<<dim3(VV / 32, 16), 256>>>(Wh, VV, 2);
    precompute_kernel<<<dim3(16, 32), 256>>>(idx, emb, Wg, bg, Wu, bu);
    step_persist_kernel<<<NCTA, 256, PS_SMEM>>>();
    ln_kernel<<<M2, 128>>>(lw, lb);
    head_kernel<<<dim3(VV / 64, M2 / 128), 256, HD_SMEM>>>(bh, out);
}

// round 10
// speedup vs baseline: 3.9310x; 1.0547x over previous
#include <cuda_runtime.h>
#include <cuda_bf16.h>
#include <math.h>
#include <stdint.h>

#define BB 8
#define SS 256
#define DD 512
#define VV 32000
#define M2 (BB * SS)
#define LN_EPS 1e-5f
#define NCTA 128u

// ---------------- device-global scratch (referenced ONLY in device code) ----------------
__device__ __align__(16) float g_Xg[M2 * DD];
__device__ __align__(16) float g_Xu[M2 * DD];
__device__ __align__(16) float g_nodes[2][DD * DD];
__device__ __align__(16) float g_cons[M2 * DD];
__device__ __align__(128) __nv_bfloat16 g_Ah[2][DD * DD];
__device__ __align__(128) __nv_bfloat16 g_Al[2][DD * DD];
__device__ __align__(128) __nv_bfloat16 g_Wgh[DD * DD];
__device__ __align__(128) __nv_bfloat16 g_Wgl[DD * DD];
__device__ __align__(128) __nv_bfloat16 g_Wuh[DD * DD];
__device__ __align__(128) __nv_bfloat16 g_Wul[DD * DD];
__device__ __align__(128) __nv_bfloat16 g_WgTh[DD * DD];
__device__ __align__(128) __nv_bfloat16 g_WgTl[DD * DD];
__device__ __align__(128) __nv_bfloat16 g_WuTh[DD * DD];
__device__ __align__(128) __nv_bfloat16 g_WuTl[DD * DD];
__device__ __align__(128) __nv_bfloat16 g_Eh[M2 * DD];
__device__ __align__(128) __nv_bfloat16 g_El[M2 * DD];
__device__ __align__(128) __nv_bfloat16 g_Lh[M2 * DD];
__device__ __align__(128) __nv_bfloat16 g_Ll[M2 * DD];
__device__ __align__(128) __nv_bfloat16 g_Whh[(size_t)VV * DD];
__device__ __align__(128) __nv_bfloat16 g_Whl[(size_t)VV * DD];
__device__ unsigned g_barB[8 * 64];   // one counter per batch, 256B apart

// ---------------- helpers (baseline ISA: sm_80-class only) ----------------
__device__ __forceinline__ uint32_t smem_u32(const void* p) {
    uint32_t a;
    asm("{ .reg .u64 t; cvta.to.shared.u64 t, %1; cvt.u32.u64 %0, t; }" : "=r"(a) : "l"(p));
    return a;
}
__device__ __forceinline__ void cp16(uint32_t dst, const void* src) {
    asm volatile("cp.async.cg.shared.global [%0], [%1], 16;" :: "r"(dst), "l"(src) : "memory");
}
#define CP_COMMIT() asm volatile("cp.async.commit_group;" ::: "memory")
#define CP_WAIT1() asm volatile("cp.async.wait_group 1;" ::: "memory")
#define CP_WAIT0() asm volatile("cp.async.wait_group 0;" ::: "memory")

__device__ __forceinline__ void mma_bf16(float* d, const uint32_t* a, const uint32_t* b) {
    asm volatile(
        "mma.sync.aligned.m16n8k16.row.col.f32.bf16.bf16.f32 "
        "{%0,%1,%2,%3}, {%4,%5,%6,%7}, {%8,%9}, {%0,%1,%2,%3};"
        : "+f"(d[0]), "+f"(d[1]), "+f"(d[2]), "+f"(d[3])
        : "r"(a[0]), "r"(a[1]), "r"(a[2]), "r"(a[3]), "r"(b[0]), "r"(b[1]));
}
// ---- 48B-stride tiles ----
__device__ __forceinline__ void ldsm48A(uint32_t* r, uint32_t base, int row0) {
    int lane = threadIdx.x & 31;
    uint32_t addr = base + (uint32_t)(row0 + (lane & 15)) * 48u + (uint32_t)((lane >> 4) << 4);
    asm volatile("ldmatrix.sync.aligned.m8n8.x4.shared.b16 {%0,%1,%2,%3}, [%4];"
        : "=r"(r[0]), "=r"(r[1]), "=r"(r[2]), "=r"(r[3]) : "r"(addr));
}
__device__ __forceinline__ void ldsm48B(uint32_t* r, uint32_t base, int n0) {
    int lane = threadIdx.x & 31;
    uint32_t addr = base + (uint32_t)(n0 + (lane & 7) + ((lane >> 4) << 3)) * 48u
                  + (uint32_t)(((lane >> 3) & 1) << 4);
    asm volatile("ldmatrix.sync.aligned.m8n8.x4.shared.b16 {%0,%1,%2,%3}, [%4];"
        : "=r"(r[0]), "=r"(r[1]), "=r"(r[2]), "=r"(r[3]) : "r"(addr));
}
// ---- 80B-stride A tiles (step kernel) ----
__device__ __forceinline__ void ldsm80A(uint32_t* r, uint32_t base, int row0, int ks) {
    int lane = threadIdx.x & 31;
    uint32_t addr = base + (uint32_t)(row0 + (lane & 15)) * 80u
                  + (uint32_t)(ks * 32 + ((lane >> 4) << 4));
    asm volatile("ldmatrix.sync.aligned.m8n8.x4.shared.b16 {%0,%1,%2,%3}, [%4];"
        : "=r"(r[0]), "=r"(r[1]), "=r"(r[2]), "=r"(r[3]) : "r"(addr));
}
// ---- 1040B-stride persistent W tiles ----
__device__ __forceinline__ void ldsmW(uint32_t* r, uint32_t base, int n0, int kc, int ks) {
    int lane = threadIdx.x & 31;
    uint32_t addr = base + (uint32_t)(n0 + (lane & 7) + ((lane >> 4) << 3)) * 1040u
                  + (uint32_t)(kc * 64 + ks * 32 + (((lane >> 3) & 1) << 4));
    asm volatile("ldmatrix.sync.aligned.m8n8.x4.shared.b16 {%0,%1,%2,%3}, [%4];"
        : "=r"(r[0]), "=r"(r[1]), "=r"(r[2]), "=r"(r[3]) : "r"(addr));
}
__device__ __forceinline__ void bsplit(float v, __nv_bfloat16& h, __nv_bfloat16& l) {
    h = __float2bfloat16(v);
    l = __float2bfloat16(v - __bfloat162float(h));
}

// ---------------- init: nodes0 + bf16 splits + barrier reset ----------------
__global__ void init_nodes_kernel(const float* __restrict__ mani) {
    if (blockIdx.x == 0 && threadIdx.x < 8) g_barB[threadIdx.x * 64] = 0u;
    int r = blockIdx.x;
    int n = r & 63;
    for (int c = threadIdx.x; c < DD; c += 256) {
        float v = mani[(size_t)n * DD + c];
        g_nodes[0][(size_t)r * DD + c] = v;
        __nv_bfloat16 h, l; bsplit(v, h, l);
        g_Ah[0][(size_t)r * DD + c] = h;
        g_Al[0][(size_t)r * DD + c] = l;
    }
}

// ---------------- gather + split: emb[idx] -> Eh/El ----------------
__global__ __launch_bounds__(128) void esplit_kernel(
    const int* __restrict__ idx, const float* __restrict__ emb)
{
    int row = blockIdx.x;
    int ix = idx[row];
    const float* src = emb + (size_t)ix * DD;
    size_t base = (size_t)row * DD;
    for (int c = threadIdx.x; c < DD; c += 128) {
        __nv_bfloat16 h, l; bsplit(src[c], h, l);
        g_Eh[base + c] = h; g_El[base + c] = l;
    }
}

// ---------------- transpose + bf16-split: W[k][n] -> O[n][k] hi/lo ----------------
// which: 0 Wg-bot, 1 Wu-bot, 2 Wh, 3 Wg-top, 4 Wu-top
__global__ __launch_bounds__(256) void wsplit_kernel(
    const float* __restrict__ W, int ncols, int which)
{
    __nv_bfloat16* Oh = (which == 0) ? g_Wgh : (which == 1) ? g_Wuh :
                        (which == 2) ? g_Whh : (which == 3) ? g_WgTh : g_WuTh;
    __nv_bfloat16* Ol = (which == 0) ? g_Wgl : (which == 1) ? g_Wul :
                        (which == 2) ? g_Whl : (which == 3) ? g_WgTl : g_WuTl;
    __shared__ float tile[32][33];
    int n0 = blockIdx.x * 32, k0 = blockIdx.y * 32;
    int tx = threadIdx.x & 31, ty = threadIdx.x >> 5;
    for (int r = ty; r < 32; r += 8)
        tile[r][tx] = W[(size_t)(k0 + r) * ncols + n0 + tx];
    __syncthreads();
    for (int r = ty; r < 32; r += 8) {
        __nv_bfloat16 h, l; bsplit(tile[tx][r], h, l);
        Oh[(size_t)(n0 + r) * DD + k0 + tx] = h;
        Ol[(size_t)(n0 + r) * DD + k0 + tx] = l;
    }
}

// ---------------- HMMA precompute: Xg/Xu = E @ W_top + bias ----------------
// grid (16 n-tiles of 32, 16 m-tiles of 128), 256 threads, 36.9KB smem (2-3 CTA/SM).
#define PR_TA 6144
#define PR_TW 1536
#define PR_STAGE (2 * PR_TA + 4 * PR_TW)   /* 18432 */
#define PR_SMEM  (2 * PR_STAGE)            /* 36864 */

__device__ __forceinline__ void pre_load(uint32_t sb, int stage, int kc, int tid, int m0, int n0) {
    uint32_t st = sb + (uint32_t)stage * PR_STAGE;
    {   // A (Eh/El): 128 rows x 2 words each
        int r = tid >> 1, c = tid & 1;
        uint32_t doff = (uint32_t)r * 48u + (uint32_t)c * 16u;
        int k0 = kc * 16 + c * 8;
        cp16(st + doff,         g_Eh + (size_t)(m0 + r) * DD + k0);
        cp16(st + PR_TA + doff, g_El + (size_t)(m0 + r) * DD + k0);
    }
    {   // W: 4 mats x 32 rows x 2 words
        int m = tid >> 6, w = tid & 63;
        int r = w >> 1, c = w & 1;
        uint32_t doff = (uint32_t)r * 48u + (uint32_t)c * 16u;
        int k0 = kc * 16 + c * 8;
        const __nv_bfloat16* W =
            (m == 0) ? g_WgTh : (m == 1) ? g_WgTl : (m == 2) ? g_WuTh : g_WuTl;
        cp16(st + 2 * PR_TA + (uint32_t)m * PR_TW + doff,
             W + (size_t)(n0 + r) * DD + k0);
    }
    CP_COMMIT();
}

__global__ __launch_bounds__(256) void pre_kernel(
    const float* __restrict__ bg, const float* __restrict__ bu)
{
    extern __shared__ __align__(16) char smem[];
    uint32_t sb = smem_u32(smem);
    int tid = threadIdx.x, wid = tid >> 5, lane = tid & 31;
    int wm = wid & 3, wn = wid >> 2;
    int n0 = blockIdx.x * 32, m0 = blockIdx.y * 128;

    float accg[2][2][4] = {}, accu[2][2][4] = {};

    pre_load(sb, 0, 0, tid, m0, n0);
    for (int c = 0; c < 32; ++c) {
        if (c < 31) { pre_load(sb, (c + 1) & 1, c + 1, tid, m0, n0); CP_WAIT1(); }
        else        { CP_WAIT0(); }
        __syncthreads();
        uint32_t st = sb + (uint32_t)(c & 1) * PR_STAGE;
        uint32_t ah[2][4], al[2][4], bf[4];
        ldsm48A(ah[0], st,         wm * 32);
        ldsm48A(ah[1], st,         wm * 32 + 16);
        ldsm48A(al[0], st + PR_TA, wm * 32);
        ldsm48A(al[1], st + PR_TA, wm * 32 + 16);
        // gate hi: (Eh + El) * Gh
        ldsm48B(bf, st + 2*PR_TA + 0*PR_TW, wn * 16);
        #pragma unroll
        for (int mt = 0; mt < 2; ++mt)
            #pragma unroll
            for (int nt = 0; nt < 2; ++nt) {
                mma_bf16(accg[mt][nt], ah[mt], &bf[nt * 2]);
                mma_bf16(accg[mt][nt], al[mt], &bf[nt * 2]);
            }
        // gate lo: Eh * Gl
        ldsm48B(bf, st + 2*PR_TA + 1*PR_TW, wn * 16);
        #pragma unroll
        for (int mt = 0; mt < 2; ++mt)
            #pragma unroll
            for (int nt = 0; nt < 2; ++nt)
                mma_bf16(accg[mt][nt], ah[mt], &bf[nt * 2]);
        // cand hi: (Eh + El) * Uh
        ldsm48B(bf, st + 2*PR_TA + 2*PR_TW, wn * 16);
        #pragma unroll
        for (int mt = 0; mt < 2; ++mt)
            #pragma unroll
            for (int nt = 0; nt < 2; ++nt) {
                mma_bf16(accu[mt][nt], ah[mt], &bf[nt * 2]);
                mma_bf16(accu[mt][nt], al[mt], &bf[nt * 2]);
            }
        // cand lo: Eh * Ul
        ldsm48B(bf, st + 2*PR_TA + 3*PR_TW, wn * 16);
        #pragma unroll
        for (int mt = 0; mt < 2; ++mt)
            #pragma unroll
            for (int nt = 0; nt < 2; ++nt)
                mma_bf16(accu[mt][nt], ah[mt], &bf[nt * 2]);
        __syncthreads();
    }

    #pragma unroll
    for (int mt = 0; mt < 2; ++mt) {
        #pragma unroll
        for (int nt = 0; nt < 2; ++nt) {
            int col = n0 + wn * 16 + nt * 8 + (lane & 3) * 2;
            float bg0 = __ldg(bg + col), bg1 = __ldg(bg + col + 1);
            float bu0 = __ldg(bu + col), bu1 = __ldg(bu + col + 1);
            #pragma unroll
            for (int h = 0; h < 2; ++h) {
                int row = m0 + wm * 32 + mt * 16 + (lane >> 2) + h * 8;
                size_t off = (size_t)row * DD + col;
                float2 og; og.x = accg[mt][nt][h*2+0] + bg0; og.y = accg[mt][nt][h*2+1] + bg1;
                float2 ou; ou.x = accu[mt][nt][h*2+0] + bu0; ou.y = accu[mt][nt][h*2+1] + bu1;
                *(float2*)(g_Xg + off) = og;
                *(float2*)(g_Xu + off) = ou;
            }
        }
    }
}

// ---------------- persistent HMMA recurrence (all 256 steps, one launch) ----------------
#define PA_STAGE 10240
#define PW_OFF   30720
#define PW_MAT   33280
#define PPART    163840
#define PS_SMEM  164352

__device__ __forceinline__ void pstepA_load(uint32_t sb, int stage, int kc, int tid,
    const __nv_bfloat16* Ah, const __nv_bfloat16* Al, int m0)
{
    uint32_t st = sb + (uint32_t)stage * PA_STAGE;
    #pragma unroll
    for (int i = 0; i < 2; ++i) {
        int j = tid + i * 256;
        int tile = j >> 8, w = j & 255, r = w >> 2, c = w & 3;
        cp16(st + (uint32_t)tile * 5120u + (uint32_t)r * 80u + (uint32_t)c * 16u,
             (tile ? Al : Ah) + (size_t)(m0 + r) * DD + kc * 32 + c * 8);
    }
    CP_COMMIT();
}

__global__ __launch_bounds__(256) void step_persist_kernel() {
    extern __shared__ __align__(16) char smem[];
    uint32_t sb = smem_u32(smem);
    int tid = threadIdx.x, wid = tid >> 5, lane = tid & 31;
    int wm = wid & 3, wn = wid >> 2;
    int b = blockIdx.x >> 4;
    int m0 = b * 64;
    int n0 = (blockIdx.x & 15) * 32;
    float* part = (float*)(smem + PPART);
    unsigned* bar = &g_barB[b * 64];

    // ---- load persistent W tiles ----
    for (int j = tid; j < 8192; j += 256) {
        int m = j >> 11, w = j & 2047, r = w >> 6, c = w & 63;
        const __nv_bfloat16* W =
            (m == 0) ? g_Wgh : (m == 1) ? g_Wgl : (m == 2) ? g_Wuh : g_Wul;
        cp16(sb + PW_OFF + (uint32_t)m * PW_MAT + (uint32_t)r * 1040u + (uint32_t)c * 16u,
             W + (size_t)(n0 + r) * DD + c * 8);
    }
    CP_COMMIT();
    CP_WAIT0();
    __syncthreads();

    uint32_t Wb = sb + PW_OFF;

    for (int t = 0; t < SS; ++t) {
        int sIn = t & 1, sOut = sIn ^ 1;
        const __nv_bfloat16* Ah = g_Ah[sIn];
        const __nv_bfloat16* Al = g_Al[sIn];

        float accg[2][4] = {}, accu[2][4] = {};

        pstepA_load(sb, 0, 0, tid, Ah, Al, m0);
        pstepA_load(sb, 1, 1, tid, Ah, Al, m0);
        for (int c = 0; c < 16; ++c) {
            if (c < 15) CP_WAIT1(); else CP_WAIT0();
            __syncthreads();
            if (c + 2 < 16) pstepA_load(sb, (c + 2) % 3, c + 2, tid, Ah, Al, m0);
            uint32_t st = sb + (uint32_t)(c % 3) * PA_STAGE;
            #pragma unroll
            for (int ks = 0; ks < 2; ++ks) {
                uint32_t ah[4], al[4], bf[4];
                ldsm80A(ah, st,        wm * 16, ks);
                ldsm80A(al, st + 5120, wm * 16, ks);
                ldsmW(bf, Wb,              wn * 16, c, ks);
                #pragma unroll
                for (int nt = 0; nt < 2; ++nt) {
                    mma_bf16(accg[nt], ah, &bf[nt * 2]);
                    mma_bf16(accg[nt], al, &bf[nt * 2]);
                }
                ldsmW(bf, Wb + PW_MAT,     wn * 16, c, ks);
                #pragma unroll
                for (int nt = 0; nt < 2; ++nt)
                    mma_bf16(accg[nt], ah, &bf[nt * 2]);
                ldsmW(bf, Wb + 2 * PW_MAT, wn * 16, c, ks);
                #pragma unroll
                for (int nt = 0; nt < 2; ++nt) {
                    mma_bf16(accu[nt], ah, &bf[nt * 2]);
                    mma_bf16(accu[nt], al, &bf[nt * 2]);
                }
                ldsmW(bf, Wb + 3 * PW_MAT, wn * 16, c, ks);
                #pragma unroll
                for (int nt = 0; nt < 2; ++nt)
                    mma_bf16(accu[nt], ah, &bf[nt * 2]);
            }
        }

        // ---- epilogue ----
        int r0 = wm * 16 + (lane >> 2);
        size_t xb = (size_t)(b * SS + t) * DD;
        const float* nodesIn  = g_nodes[sIn];
        float*       nodesOut = g_nodes[sOut];
        __nv_bfloat16* nH = g_Ah[sOut];
        __nv_bfloat16* nL = g_Al[sOut];

        #pragma unroll
        for (int nt = 0; nt < 2; ++nt) {
            int col = n0 + wn * 16 + nt * 8 + (lane & 3) * 2;
            float xg0 = g_Xg[xb + col], xg1 = g_Xg[xb + col + 1];
            float xu0 = g_Xu[xb + col], xu1 = g_Xu[xb + col + 1];
            float cs0 = 0.f, cs1 = 0.f;
            #pragma unroll
            for (int h = 0; h < 2; ++h) {
                int row = m0 + r0 + h * 8;
                size_t off = (size_t)row * DD + col;
                float2 oldv = __ldcg((const float2*)(nodesIn + off));
                float gv0 = accg[nt][h * 2 + 0] + xg0;
                float gv1 = accg[nt][h * 2 + 1] + xg1;
                float cv0 = accu[nt][h * 2 + 0] + xu0;
                float cv1 = accu[nt][h * 2 + 1] + xu1;
                float g0 = 1.f / (1.f + __expf(-gv0));
                float g1 = 1.f / (1.f + __expf(-gv1));
                float e0 = __expf(2.f * cv0), e1 = __expf(2.f * cv1);
                float th0 = 1.f - 2.f / (e0 + 1.f);
                float th1 = 1.f - 2.f / (e1 + 1.f);
                float v0 = fmaf(g0, th0 - oldv.x, oldv.x);
                float v1 = fmaf(g1, th1 - oldv.y, oldv.y);
                float2 vv; vv.x = v0; vv.y = v1;
                *(float2*)(nodesOut + off) = vv;
                __nv_bfloat16 h0, l0, h1, l1;
                bsplit(v0, h0, l0); bsplit(v1, h1, l1);
                __nv_bfloat162 ph; ph.x = h0; ph.y = h1;
                __nv_bfloat162 pl; pl.x = l0; pl.y = l1;
                *(__nv_bfloat162*)(nH + off) = ph;
                *(__nv_bfloat162*)(nL + off) = pl;
                cs0 += v0; cs1 += v1;
            }
            #pragma unroll
            for (int s = 4; s <= 16; s <<= 1) {
                cs0 += __shfl_xor_sync(0xffffffffu, cs0, s);
                cs1 += __shfl_xor_sync(0xffffffffu, cs1, s);
            }
            if (lane < 4) {
                int cl = wn * 16 + nt * 8 + lane * 2;
                part[wm * 32 + cl]     = cs0;
                part[wm * 32 + cl + 1] = cs1;
            }
        }
        __syncthreads();
        if (tid < 32) {
            float s = part[tid] + part[32 + tid] + part[64 + tid] + part[96 + tid];
            g_cons[xb + n0 + tid] = s * (1.f / 64.f);
        }

        // ---- per-batch barrier (16 CTAs; monotonic counter, reset by init) ----
        __threadfence();
        __syncthreads();
        if (tid == 0) {
            atomicAdd(bar, 1u);
            unsigned target = 16u * (unsigned)(t + 1);
            while (*(volatile unsigned*)bar < target) { }
        }
        __syncthreads();
    }
}

// ---------------- layernorm -> bf16 hi/lo ----------------
__device__ __forceinline__ float warp_sum(float v) {
    v += __shfl_xor_sync(0xffffffffu, v, 16);
    v += __shfl_xor_sync(0xffffffffu, v, 8);
    v += __shfl_xor_sync(0xffffffffu, v, 4);
    v += __shfl_xor_sync(0xffffffffu, v, 2);
    v += __shfl_xor_sync(0xffffffffu, v, 1);
    return v;
}
__global__ __launch_bounds__(128) void ln_kernel(
    const float* __restrict__ lw, const float* __restrict__ lb)
{
    int r = blockIdx.x, tid = threadIdx.x;
    const float* x = g_cons + (size_t)r * DD;
    float4 v = *(const float4*)(x + tid * 4);
    __shared__ float red[4];
    float s = warp_sum(v.x + v.y + v.z + v.w);
    if ((tid & 31) == 0) red[tid >> 5] = s;
    __syncthreads();
    float mu = (red[0] + red[1] + red[2] + red[3]) * (1.f / DD);
    __syncthreads();
    float d0 = v.x - mu, d1 = v.y - mu, d2 = v.z - mu, d3 = v.w - mu;
    float ss = warp_sum(d0*d0 + d1*d1 + d2*d2 + d3*d3);
    if ((tid & 31) == 0) red[tid >> 5] = ss;
    __syncthreads();
    float inv = rsqrtf((red[0]+red[1]+red[2]+red[3]) * (1.f / DD) + LN_EPS);
    float4 w = *(const float4*)(lw + tid * 4);
    float4 bb = *(const float4*)(lb + tid * 4);
    float o[4] = { d0*inv*w.x + bb.x, d1*inv*w.y + bb.y, d2*inv*w.z + bb.z, d3*inv*w.w + bb.w };
    size_t base = (size_t)r * DD + tid * 4;
    #pragma unroll
    for (int i = 0; i < 4; ++i) {
        __nv_bfloat16 h, l; bsplit(o[i], h, l);
        g_Lh[base + i] = h; g_Ll[base + i] = l;
    }
}

// ---------------- HMMA output head: 128M x 64N tiles (proven) ----------------
#define HD_TA 6144
#define HD_TB 3072
#define HD_STAGE (2 * HD_TA + 2 * HD_TB)
#define HD_SMEM  (2 * HD_STAGE)

__device__ __forceinline__ void head_load(uint32_t sb, int stage, int kc, int tid, int m0, int n0) {
    uint32_t st = sb + stage * HD_STAGE;
    {
        int r = tid >> 1, c = tid & 1;
        uint32_t doff = (uint32_t)r * 48u + (uint32_t)c * 16u;
        int k0 = kc * 16 + c * 8;
        cp16(st + doff,         g_Lh + (size_t)(m0 + r) * DD + k0);
        cp16(st + HD_TA + doff, g_Ll + (size_t)(m0 + r) * DD + k0);
    }
    {
        int half = tid >> 7, w = tid & 127;
        int r = w >> 1, c = w & 1;
        uint32_t doff = (uint32_t)r * 48u + (uint32_t)c * 16u;
        int k0 = kc * 16 + c * 8;
        const __nv_bfloat16* src = (half ? g_Whl : g_Whh) + (size_t)(n0 + r) * DD + k0;
        cp16(st + 2 * HD_TA + (uint32_t)half * HD_TB + doff, src);
    }
    CP_COMMIT();
}

__global__ __launch_bounds__(256) void head_kernel(
    const float* __restrict__ bh, float* __restrict__ out)
{
    extern __shared__ __align__(16) char smem[];
    uint32_t sb = smem_u32(smem);
    int tid = threadIdx.x, wid = tid >> 5, lane = tid & 31;
    int wm = wid & 3, wn = wid >> 2;
    int n0 = blockIdx.x * 64, m0 = blockIdx.y * 128;

    float acc[2][4][4];
    #pragma unroll
    for (int i = 0; i < 2; ++i)
        #pragma unroll
        for (int j = 0; j < 4; ++j)
            #pragma unroll
            for (int k = 0; k < 4; ++k) acc[i][j][k] = 0.f;

    head_load(sb, 0, 0, tid, m0, n0);
    for (int c = 0; c < 32; ++c) {
        if (c < 31) { head_load(sb, (c + 1) & 1, c + 1, tid, m0, n0); CP_WAIT1(); }
        else        { CP_WAIT0(); }
        __syncthreads();
        uint32_t st = sb + (c & 1) * HD_STAGE;
        uint32_t ah[2][4], al[2][4], b0[4], b1[4];
        ldsm48A(ah[0], st,         wm * 32);
        ldsm48A(ah[1], st,         wm * 32 + 16);
        ldsm48A(al[0], st + HD_TA, wm * 32);
        ldsm48A(al[1], st + HD_TA, wm * 32 + 16);
        ldsm48B(b0, st + 2*HD_TA,  wn * 32);
        ldsm48B(b1, st + 2*HD_TA,  wn * 32 + 16);
        #pragma unroll
        for (int nt = 0; nt < 4; ++nt) {
            const uint32_t* bp = (nt < 2) ? &b0[nt * 2] : &b1[(nt & 1) * 2];
            #pragma unroll
            for (int mt = 0; mt < 2; ++mt) {
                mma_bf16(acc[mt][nt], ah[mt], bp);
                mma_bf16(acc[mt][nt], al[mt], bp);
            }
        }
        ldsm48B(b0, st + 2*HD_TA + HD_TB, wn * 32);
        ldsm48B(b1, st + 2*HD_TA + HD_TB, wn * 32 + 16);
        #pragma unroll
        for (int nt = 0; nt < 4; ++nt) {
            const uint32_t* bp = (nt < 2) ? &b0[nt * 2] : &b1[(nt & 1) * 2];
            #pragma unroll
            for (int mt = 0; mt < 2; ++mt)
                mma_bf16(acc[mt][nt], ah[mt], bp);
        }
        __syncthreads();
    }

    #pragma unroll
    for (int mt = 0; mt < 2; ++mt) {
        #pragma unroll
        for (int nt = 0; nt < 4; ++nt) {
            int col = n0 + wn * 32 + nt * 8 + (lane & 3) * 2;
            float b0v = __ldg(bh + col), b1v = __ldg(bh + col + 1);
            #pragma unroll
            for (int h = 0; h < 2; ++h) {
                int row = m0 + wm * 32 + mt * 16 + (lane >> 2) + h * 8;
                float2 o;
                o.x = acc[mt][nt][h * 2 + 0] + b0v;
                o.y = acc[mt][nt][h * 2 + 1] + b1v;
                *(float2*)(out + (size_t)row * VV + col) = o;
            }
        }
    }
}

// ---------------- launch ----------------
extern "C" void kernel_launch(void* const* d_in, const int* in_sizes, int n_in,
                              void* d_out, int out_size)
{
    const int*   idx  = (const int*)  d_in[0];
    const float* emb  = (const float*)d_in[1];
    const float* mani = (const float*)d_in[2];
    const float* Wg   = (const float*)d_in[3];
    const float* bg   = (const float*)d_in[4];
    const float* Wu   = (const float*)d_in[5];
    const float* bu   = (const float*)d_in[6];
    const float* lw   = (const float*)d_in[7];
    const float* lb   = (const float*)d_in[8];
    const float* Wh   = (const float*)d_in[9];
    const float* bh   = (const float*)d_in[10];
    float* out = (float*)d_out;

    cudaFuncSetAttribute(step_persist_kernel, cudaFuncAttributeMaxDynamicSharedMemorySize, PS_SMEM);

    init_nodes_kernel<<<512, 256>>>(mani);
    esplit_kernel<<<M2, 128>>>(idx, emb);
    wsplit_kernel<<<dim3(16, 16), 256>>>(Wg + (size_t)DD * DD, DD, 0);
    wsplit_kernel<<<dim3(16, 16), 256>>>(Wu + (size_t)DD * DD, DD, 1);
    wsplit_kernel<<<dim3(VV / 32, 16), 256>>>(Wh, VV, 2);
    wsplit_kernel<<<dim3(16, 16), 256>>>(Wg, DD, 3);
    wsplit_kernel<<<dim3(16, 16), 256>>>(Wu, DD, 4);
    pre_kernel<<<dim3(16, 16), 256, PR_SMEM>>>(bg, bu);
    step_persist_kernel<<<NCTA, 256, PS_SMEM>>>();
    ln_kernel<<<M2, 128>>>(lw, lb);
    head_kernel<<<dim3(VV / 64, M2 / 128), 256, HD_SMEM>>>(bh, out);
}